// round 1
// baseline (speedup 1.0000x reference)
#include <cuda_runtime.h>
#include <math.h>
#include <stdint.h>

// ---------------------------------------------------------------------------
// BigBirdBoxHead: 2-layer pre-LN transformer encoder (S=49, D=1024, H=2) +
// flatten->linear(50176->1024)->relu head.  Pure fp32 baseline.
// ---------------------------------------------------------------------------

#define BATCH 256
#define SEQ   49
#define NTOK  (BATCH*SEQ)      // 12544
#define DM    1024
#define HDIM  512
#define NHEAD 2
#define KTOT  (SEQ*DM)         // 50176
#define EPS   1e-5f

// Scratch (static device globals; allocation APIs are forbidden)
__device__ float g_h  [NTOK*DM];
__device__ float g_hn [NTOK*DM];
__device__ float g_q  [NTOK*DM];
__device__ float g_k  [NTOK*DM];
__device__ float g_v  [NTOK*DM];
__device__ float g_ctx[NTOK*DM];
__device__ float g_t  [NTOK*DM];
__device__ float g_acc[BATCH*DM];

// ---------------------------------------------------------------------------
// Embed: h[b,s,d] = x[b,d,s] + pos[s,d]   (transpose via smem tile)
// ---------------------------------------------------------------------------
__global__ void embed_kernel(const float* __restrict__ x,
                             const float* __restrict__ pos) {
    __shared__ float tile[32][33];
    int b  = blockIdx.z;
    int s0 = blockIdx.y * 32;
    int d0 = blockIdx.x * 32;
    int tx = threadIdx.x, ty = threadIdx.y;

    if (s0 + tx < SEQ)
        tile[ty][tx] = x[(size_t)b*DM*SEQ + (size_t)(d0+ty)*SEQ + (s0+tx)];
    __syncthreads();
    int ss = s0 + ty, dd = d0 + tx;
    if (ss < SEQ)
        g_h[((size_t)b*SEQ + ss)*DM + dd] = tile[tx][ty] + pos[(size_t)ss*DM + dd];
}

// ---------------------------------------------------------------------------
// LayerNorm per row of 1024, block=256
// ---------------------------------------------------------------------------
__global__ void ln_kernel(const float* __restrict__ in, float* __restrict__ out,
                          const float* __restrict__ sc, const float* __restrict__ bi) {
    int r = blockIdx.x;
    const float* row = in + (size_t)r*DM;
    float v[4];
    float s = 0.f, sq = 0.f;
#pragma unroll
    for (int i = 0; i < 4; i++) {
        v[i] = row[threadIdx.x + i*256];
        s += v[i]; sq += v[i]*v[i];
    }
#pragma unroll
    for (int o = 16; o > 0; o >>= 1) {
        s  += __shfl_xor_sync(0xffffffffu, s,  o);
        sq += __shfl_xor_sync(0xffffffffu, sq, o);
    }
    __shared__ float sh[2][8];
    int w = threadIdx.x >> 5, l = threadIdx.x & 31;
    if (l == 0) { sh[0][w] = s; sh[1][w] = sq; }
    __syncthreads();
    s = 0.f; sq = 0.f;
#pragma unroll
    for (int i = 0; i < 8; i++) { s += sh[0][i]; sq += sh[1][i]; }
    float mean = s * (1.f/1024.f);
    float var  = sq * (1.f/1024.f) - mean*mean;
    float rstd = rsqrtf(var + EPS);
#pragma unroll
    for (int i = 0; i < 4; i++) {
        int d = threadIdx.x + i*256;
        out[(size_t)r*DM + d] = (v[i] - mean) * rstd * sc[d] + bi[d];
    }
}

// ---------------------------------------------------------------------------
// gelu (tanh approximation, matches jax.nn.gelu approximate=True)
// ---------------------------------------------------------------------------
__device__ __forceinline__ float gelu_tanh(float x) {
    float x3 = x*x*x;
    return 0.5f * x * (1.f + tanhf(0.7978845608028654f * (x + 0.044715f*x3)));
}

// ---------------------------------------------------------------------------
// Generic tiled SGEMM: C = epi(A[M,K] @ B[K,N])
// BM=BN=64, BK=16, 256 threads, 4x4 micro-tile.
// Epilogue order: +bias, gelu, +residual  (covers all uses)
// M,N,K all multiples of tile sizes here.
// ---------------------------------------------------------------------------
template<bool RES, bool BIAS, bool GELU>
__global__ void gemm64(const float* __restrict__ A, const float* __restrict__ Bw,
                       const float* __restrict__ Rs, const float* __restrict__ bias,
                       float* __restrict__ C, int M, int N, int K) {
    __shared__ float As[64][16];
    __shared__ float Bs[16][64];
    int bm = blockIdx.y * 64;
    int bn = blockIdx.x * 64;
    int tx = threadIdx.x & 15;   // 0..15 -> n
    int ty = threadIdx.x >> 4;   // 0..15 -> m
    float acc[4][4] = {};

    for (int k0 = 0; k0 < K; k0 += 16) {
#pragma unroll
        for (int i = 0; i < 4; i++) {
            int e = threadIdx.x + i*256;
            int r = e >> 4, c = e & 15;
            As[r][c] = A[(size_t)(bm + r)*K + k0 + c];
        }
#pragma unroll
        for (int i = 0; i < 4; i++) {
            int e = threadIdx.x + i*256;
            int r = e >> 6, c = e & 63;
            Bs[r][c] = Bw[(size_t)(k0 + r)*N + bn + c];
        }
        __syncthreads();
#pragma unroll
        for (int kk = 0; kk < 16; kk++) {
            float a0 = As[ty*4+0][kk];
            float a1 = As[ty*4+1][kk];
            float a2 = As[ty*4+2][kk];
            float a3 = As[ty*4+3][kk];
            float4 b4 = *reinterpret_cast<const float4*>(&Bs[kk][tx*4]);
            acc[0][0] += a0*b4.x; acc[0][1] += a0*b4.y; acc[0][2] += a0*b4.z; acc[0][3] += a0*b4.w;
            acc[1][0] += a1*b4.x; acc[1][1] += a1*b4.y; acc[1][2] += a1*b4.z; acc[1][3] += a1*b4.w;
            acc[2][0] += a2*b4.x; acc[2][1] += a2*b4.y; acc[2][2] += a2*b4.z; acc[2][3] += a2*b4.w;
            acc[3][0] += a3*b4.x; acc[3][1] += a3*b4.y; acc[3][2] += a3*b4.z; acc[3][3] += a3*b4.w;
        }
        __syncthreads();
    }

    float4 bb = make_float4(0.f,0.f,0.f,0.f);
    if (BIAS) bb = *reinterpret_cast<const float4*>(&bias[bn + tx*4]);
#pragma unroll
    for (int i = 0; i < 4; i++) {
        int row = bm + ty*4 + i;
        size_t off = (size_t)row*N + bn + tx*4;
        float4 o = make_float4(acc[i][0], acc[i][1], acc[i][2], acc[i][3]);
        if (BIAS) { o.x += bb.x; o.y += bb.y; o.z += bb.z; o.w += bb.w; }
        if (GELU) { o.x = gelu_tanh(o.x); o.y = gelu_tanh(o.y);
                    o.z = gelu_tanh(o.z); o.w = gelu_tanh(o.w); }
        if (RES) {
            float4 r4 = *reinterpret_cast<const float4*>(&Rs[off]);
            o.x += r4.x; o.y += r4.y; o.z += r4.z; o.w += r4.w;
        }
        *reinterpret_cast<float4*>(&C[off]) = o;
    }
}

// ---------------------------------------------------------------------------
// Fused attention per (b, head): scores -> softmax -> ctx.  512 threads.
// ---------------------------------------------------------------------------
__global__ void attn_kernel() {
    int bh = blockIdx.x;
    int b = bh >> 1, h = bh & 1;
    __shared__ float sc[SEQ*SEQ];      // 2401
    __shared__ float qs[SEQ][65];
    __shared__ float ks[SEQ][65];
    int tid = threadIdx.x;

    const float* qbase = g_q + ((size_t)b*SEQ)*DM + h*HDIM;
    const float* kbase = g_k + ((size_t)b*SEQ)*DM + h*HDIM;
    const float* vbase = g_v + ((size_t)b*SEQ)*DM + h*HDIM;

    // --- scores: 2401 pairs, 5 per thread, chunked over d ---
    float acc[5] = {0.f,0.f,0.f,0.f,0.f};
    int qi[5], ki[5];
#pragma unroll
    for (int j = 0; j < 5; j++) {
        int p = tid + j*512; if (p > 2400) p = 2400;
        qi[j] = p / SEQ; ki[j] = p % SEQ;
    }
    for (int c0 = 0; c0 < HDIM; c0 += 64) {
        for (int e = tid; e < SEQ*64; e += 512) {
            int r = e >> 6, c = e & 63;
            qs[r][c] = qbase[(size_t)r*DM + c0 + c];
            ks[r][c] = kbase[(size_t)r*DM + c0 + c];
        }
        __syncthreads();
#pragma unroll 4
        for (int c = 0; c < 64; c++) {
#pragma unroll
            for (int j = 0; j < 5; j++)
                acc[j] += qs[qi[j]][c] * ks[ki[j]][c];
        }
        __syncthreads();
    }
    const float scale = 0.044194173824159216f;  // 1/sqrt(512)
#pragma unroll
    for (int j = 0; j < 5; j++) {
        int p = tid + j*512;
        if (p < SEQ*SEQ) sc[p] = acc[j] * scale;
    }
    __syncthreads();

    // --- softmax: one thread per row ---
    if (tid < SEQ) {
        float m = -1e30f;
        for (int k = 0; k < SEQ; k++) m = fmaxf(m, sc[tid*SEQ + k]);
        float ssum = 0.f;
        for (int k = 0; k < SEQ; k++) {
            float e = expf(sc[tid*SEQ + k] - m);
            sc[tid*SEQ + k] = e; ssum += e;
        }
        float inv = 1.f / ssum;
        for (int k = 0; k < SEQ; k++) sc[tid*SEQ + k] *= inv;
    }
    __syncthreads();

    // --- ctx: thread = one of 512 head-dim columns; 49 accumulators ---
    {
        float a[SEQ];
#pragma unroll
        for (int q = 0; q < SEQ; q++) a[q] = 0.f;
        for (int k = 0; k < SEQ; k++) {
            float vv = vbase[(size_t)k*DM + tid];
#pragma unroll
            for (int q = 0; q < SEQ; q++)
                a[q] += sc[q*SEQ + k] * vv;
        }
        float* cb = g_ctx + ((size_t)b*SEQ)*DM + h*HDIM + tid;
#pragma unroll
        for (int q = 0; q < SEQ; q++)
            cb[(size_t)q*DM] = a[q];
    }
}

// ---------------------------------------------------------------------------
// Head GEMM: out[256,1024] += hn[256,50176] @ W[50176,1024]
// BM=256 (full M, so W streams from DRAM exactly once), BN=128, BK=8,
// split-K over 32 chunks of 1568, atomicAdd reduction into g_acc.
// 512 threads, 8x8 micro-tile.
// ---------------------------------------------------------------------------
__global__ void __launch_bounds__(512) head_kernel(const float* __restrict__ W) {
    __shared__ float As[8][260];    // pitch 260 -> 16B-aligned rows, conflict-free
    __shared__ float Bs[8][128];
    int bn = blockIdx.x * 128;
    int k0 = blockIdx.y * 1568;
    int tid = threadIdx.x;
    int tm = tid >> 4;   // 0..31  -> rows tm*8..
    int tn = tid & 15;   // 0..15  -> cols tn*8..
    float acc[8][8] = {};

    for (int kc = 0; kc < 1568; kc += 8) {
        int kb = k0 + kc;
#pragma unroll
        for (int i = 0; i < 4; i++) {
            int e = tid + i*512;
            int m = e >> 3, c = e & 7;
            As[c][m] = g_hn[(size_t)m*KTOT + kb + c];
        }
#pragma unroll
        for (int i = 0; i < 2; i++) {
            int e = tid + i*512;
            int r = e >> 7, c = e & 127;
            Bs[r][c] = W[(size_t)(kb + r)*DM + bn + c];
        }
        __syncthreads();
#pragma unroll
        for (int kk = 0; kk < 8; kk++) {
            float4 a0 = *reinterpret_cast<const float4*>(&As[kk][tm*8]);
            float4 a1 = *reinterpret_cast<const float4*>(&As[kk][tm*8+4]);
            float4 b0 = *reinterpret_cast<const float4*>(&Bs[kk][tn*8]);
            float4 b1 = *reinterpret_cast<const float4*>(&Bs[kk][tn*8+4]);
            float am[8] = {a0.x,a0.y,a0.z,a0.w,a1.x,a1.y,a1.z,a1.w};
            float bm_[8] = {b0.x,b0.y,b0.z,b0.w,b1.x,b1.y,b1.z,b1.w};
#pragma unroll
            for (int i = 0; i < 8; i++)
#pragma unroll
                for (int j = 0; j < 8; j++)
                    acc[i][j] += am[i] * bm_[j];
        }
        __syncthreads();
    }
#pragma unroll
    for (int i = 0; i < 8; i++) {
        int row = tm*8 + i;
#pragma unroll
        for (int j = 0; j < 8; j++)
            atomicAdd(&g_acc[(size_t)row*DM + bn + tn*8 + j], acc[i][j]);
    }
}

__global__ void zero_acc_kernel() {
    g_acc[blockIdx.x*256 + threadIdx.x] = 0.f;
}

__global__ void head_fin_kernel(const float* __restrict__ hb, float* __restrict__ out) {
    int i = blockIdx.x*256 + threadIdx.x;
    float v = g_acc[i] + hb[i & (DM-1)];
    out[i] = v > 0.f ? v : 0.f;
}

// ---------------------------------------------------------------------------
// Launch
// ---------------------------------------------------------------------------
extern "C" void kernel_launch(void* const* d_in, const int* in_sizes, int n_in,
                              void* d_out, int out_size) {
    const float* x     = (const float*)d_in[0];
    const float* pos   = (const float*)d_in[1];
    const float* ln1_s = (const float*)d_in[2];
    const float* ln1_b = (const float*)d_in[3];
    const float* wq    = (const float*)d_in[4];
    const float* wk    = (const float*)d_in[5];
    const float* wv    = (const float*)d_in[6];
    const float* wo    = (const float*)d_in[7];
    const float* ln2_s = (const float*)d_in[8];
    const float* ln2_b = (const float*)d_in[9];
    const float* w1    = (const float*)d_in[10];
    const float* b1    = (const float*)d_in[11];
    const float* w2    = (const float*)d_in[12];
    const float* b2    = (const float*)d_in[13];
    const float* lnf_s = (const float*)d_in[14];
    const float* lnf_b = (const float*)d_in[15];
    const float* hw    = (const float*)d_in[16];
    const float* hb    = (const float*)d_in[17];
    float* out = (float*)d_out;

    float *h, *hn, *q, *k, *v, *ctx, *t;
    cudaGetSymbolAddress((void**)&h,   g_h);
    cudaGetSymbolAddress((void**)&hn,  g_hn);
    cudaGetSymbolAddress((void**)&q,   g_q);
    cudaGetSymbolAddress((void**)&k,   g_k);
    cudaGetSymbolAddress((void**)&v,   g_v);
    cudaGetSymbolAddress((void**)&ctx, g_ctx);
    cudaGetSymbolAddress((void**)&t,   g_t);

    embed_kernel<<<dim3(32, 2, BATCH), dim3(32, 32)>>>(x, pos);

    dim3 gg(DM/64, NTOK/64);   // (16, 196)
    for (int i = 0; i < 2; i++) {
        size_t wofs = (size_t)i*DM*DM;
        ln_kernel<<<NTOK, 256>>>(h, hn, ln1_s + i*DM, ln1_b + i*DM);
        gemm64<false,false,false><<<gg, 256>>>(hn, wq + wofs, nullptr, nullptr, q, NTOK, DM, DM);
        gemm64<false,false,false><<<gg, 256>>>(hn, wk + wofs, nullptr, nullptr, k, NTOK, DM, DM);
        gemm64<false,false,false><<<gg, 256>>>(hn, wv + wofs, nullptr, nullptr, v, NTOK, DM, DM);
        attn_kernel<<<BATCH*NHEAD, 512>>>();
        gemm64<true,false,false><<<gg, 256>>>(ctx, wo + wofs, h, nullptr, h, NTOK, DM, DM);
        ln_kernel<<<NTOK, 256>>>(h, hn, ln2_s + i*DM, ln2_b + i*DM);
        gemm64<false,true,true><<<gg, 256>>>(hn, w1 + wofs, nullptr, b1 + i*DM, t, NTOK, DM, DM);
        gemm64<true,true,false><<<gg, 256>>>(t, w2 + wofs, h, b2 + i*DM, h, NTOK, DM, DM);
    }
    ln_kernel<<<NTOK, 256>>>(h, hn, lnf_s, lnf_b);

    zero_acc_kernel<<<BATCH*DM/256, 256>>>();
    head_kernel<<<dim3(DM/128, 32), 512>>>(hw);
    head_fin_kernel<<<BATCH*DM/256, 256>>>(hb, out);
}

// round 4
// speedup vs baseline: 1.4633x; 1.4633x over previous
#include <cuda_runtime.h>
#include <mma.h>
#include <math.h>
#include <stdint.h>

using namespace nvcuda;

#define BATCH 256
#define SEQ   49
#define NTOK  (BATCH*SEQ)      // 12544
#define DM    1024
#define HDIM  512
#define NHEAD 2
#define KTOT  (SEQ*DM)         // 50176
#define EPS   1e-5f

// Scratch (static device globals; allocation APIs are forbidden)
__device__ float g_h  [NTOK*DM];
__device__ float g_hn [NTOK*DM];
__device__ float g_q  [NTOK*DM];
__device__ float g_k  [NTOK*DM];
__device__ float g_v  [NTOK*DM];
__device__ float g_ctx[NTOK*DM];
__device__ float g_t  [NTOK*DM];
__device__ float g_acc[BATCH*DM];

__device__ __forceinline__ float to_tf32(float x) {
    uint32_t r;
    asm("cvt.rna.tf32.f32 %0, %1;" : "=r"(r) : "f"(x));
    return __uint_as_float(r);
}

// ---------------------------------------------------------------------------
// Embed: h[b,s,d] = x[b,d,s] + pos[s,d]
// ---------------------------------------------------------------------------
__global__ void embed_kernel(const float* __restrict__ x,
                             const float* __restrict__ pos) {
    __shared__ float tile[32][33];
    int b  = blockIdx.z;
    int s0 = blockIdx.y * 32;
    int d0 = blockIdx.x * 32;
    int tx = threadIdx.x, ty = threadIdx.y;

    if (s0 + tx < SEQ)
        tile[ty][tx] = x[(size_t)b*DM*SEQ + (size_t)(d0+ty)*SEQ + (s0+tx)];
    __syncthreads();
    int ss = s0 + ty, dd = d0 + tx;
    if (ss < SEQ)
        g_h[((size_t)b*SEQ + ss)*DM + dd] = tile[tx][ty] + pos[(size_t)ss*DM + dd];
}

// ---------------------------------------------------------------------------
// LayerNorm per row of 1024
// ---------------------------------------------------------------------------
__global__ void ln_kernel(const float* __restrict__ in, float* __restrict__ out,
                          const float* __restrict__ sc, const float* __restrict__ bi) {
    int r = blockIdx.x;
    const float* row = in + (size_t)r*DM;
    float v[4];
    float s = 0.f, sq = 0.f;
#pragma unroll
    for (int i = 0; i < 4; i++) {
        v[i] = row[threadIdx.x + i*256];
        s += v[i]; sq += v[i]*v[i];
    }
#pragma unroll
    for (int o = 16; o > 0; o >>= 1) {
        s  += __shfl_xor_sync(0xffffffffu, s,  o);
        sq += __shfl_xor_sync(0xffffffffu, sq, o);
    }
    __shared__ float sh[2][8];
    int w = threadIdx.x >> 5, l = threadIdx.x & 31;
    if (l == 0) { sh[0][w] = s; sh[1][w] = sq; }
    __syncthreads();
    s = 0.f; sq = 0.f;
#pragma unroll
    for (int i = 0; i < 8; i++) { s += sh[0][i]; sq += sh[1][i]; }
    float mean = s * (1.f/1024.f);
    float var  = sq * (1.f/1024.f) - mean*mean;
    float rstd = rsqrtf(var + EPS);
#pragma unroll
    for (int i = 0; i < 4; i++) {
        int d = threadIdx.x + i*256;
        out[(size_t)r*DM + d] = (v[i] - mean) * rstd * sc[d] + bi[d];
    }
}

__device__ __forceinline__ float gelu_tanh(float x) {
    float x3 = x*x*x;
    return 0.5f * x * (1.f + tanhf(0.7978845608028654f * (x + 0.044715f*x3)));
}

// ---------------------------------------------------------------------------
// TF32 WMMA GEMM: C = epi(A[M,K] @ B[K,N]).  BM=128, BN=128, BK=16.
// 256 threads = 8 warps in 4x2; warp tile 32x64 = 2x4 wmma(16x16x8) tiles.
// Double-buffered smem, register prefetch.  Inputs pre-rounded to tf32.
// ---------------------------------------------------------------------------
#define ALD 20    // 128x16 A tile, row pitch 20 floats
#define BLD 132   // 16x128 B tile, row pitch 132 floats
#define ASZ (128*ALD)   // 2560
#define BSZ (16*BLD)    // 2112
#define ELD 68          // epilogue scratch pitch

template<bool RES, bool BIAS, bool GELU>
__global__ void __launch_bounds__(256) gemm_tc(
        const float* __restrict__ A, const float* __restrict__ Bw,
        const float* __restrict__ Rs, const float* __restrict__ bias,
        float* __restrict__ C, int M, int N, int K) {
    __shared__ __align__(32) float sm[2*ASZ + 2*BSZ];   // 37376 B
    float* AsBase = sm;
    float* BsBase = sm + 2*ASZ;

    int bm = blockIdx.y * 128;
    int bn = blockIdx.x * 128;
    int tid = threadIdx.x;
    int warp = tid >> 5, lane = tid & 31;
    int wm = warp & 3;    // rows wm*32
    int wn = warp >> 2;   // cols wn*64

    wmma::fragment<wmma::accumulator,16,16,8,float> acc[2][4];
#pragma unroll
    for (int i = 0; i < 2; i++)
#pragma unroll
        for (int j = 0; j < 4; j++) wmma::fill_fragment(acc[i][j], 0.f);

    float4 ra[2], rb[2];

    auto loadA = [&](int k0) {
#pragma unroll
        for (int i = 0; i < 2; i++) {
            int e = tid + i*256;
            int row = e >> 2, c4 = (e & 3) * 4;
            ra[i] = *reinterpret_cast<const float4*>(&A[(size_t)(bm+row)*K + k0 + c4]);
        }
    };
    auto loadB = [&](int k0) {
#pragma unroll
        for (int i = 0; i < 2; i++) {
            int e = tid + i*256;
            int row = e >> 5, c4 = (e & 31) * 4;
            rb[i] = *reinterpret_cast<const float4*>(&Bw[(size_t)(k0+row)*N + bn + c4]);
        }
    };
    auto stage = [&](int buf) {
        float* As = AsBase + buf*ASZ;
        float* Bs = BsBase + buf*BSZ;
#pragma unroll
        for (int i = 0; i < 2; i++) {
            int e = tid + i*256;
            int row = e >> 2, c4 = (e & 3) * 4;
            float* p = &As[row*ALD + c4];
            p[0]=to_tf32(ra[i].x); p[1]=to_tf32(ra[i].y);
            p[2]=to_tf32(ra[i].z); p[3]=to_tf32(ra[i].w);
        }
#pragma unroll
        for (int i = 0; i < 2; i++) {
            int e = tid + i*256;
            int row = e >> 5, c4 = (e & 31) * 4;
            float* p = &Bs[row*BLD + c4];
            p[0]=to_tf32(rb[i].x); p[1]=to_tf32(rb[i].y);
            p[2]=to_tf32(rb[i].z); p[3]=to_tf32(rb[i].w);
        }
    };

    loadA(0); loadB(0);
    stage(0);
    __syncthreads();

    int buf = 0;
    int T = K >> 4;
#pragma unroll 1
    for (int t = 0; t < T; t++) {
        if (t + 1 < T) { loadA((t+1)<<4); loadB((t+1)<<4); }
        {
            float* As = AsBase + buf*ASZ;
            float* Bs = BsBase + buf*BSZ;
#pragma unroll
            for (int ks = 0; ks < 2; ks++) {
                wmma::fragment<wmma::matrix_a,16,16,8,wmma::precision::tf32,wmma::row_major> fa[2];
                wmma::fragment<wmma::matrix_b,16,16,8,wmma::precision::tf32,wmma::row_major> fb[4];
#pragma unroll
                for (int i = 0; i < 2; i++)
                    wmma::load_matrix_sync(fa[i], &As[(wm*32 + i*16)*ALD + ks*8], ALD);
#pragma unroll
                for (int j = 0; j < 4; j++)
                    wmma::load_matrix_sync(fb[j], &Bs[(ks*8)*BLD + wn*64 + j*16], BLD);
#pragma unroll
                for (int i = 0; i < 2; i++)
#pragma unroll
                    for (int j = 0; j < 4; j++)
                        wmma::mma_sync(acc[i][j], fa[i], fb[j], acc[i][j]);
            }
        }
        if (t + 1 < T) {
            stage(buf ^ 1);
            __syncthreads();
            buf ^= 1;
        }
    }
    __syncthreads();   // before smem reuse as epilogue scratch

    float* sc = sm + warp * (16*ELD);   // 8 warps * 1088 floats = 8704 <= 9344
#pragma unroll 1
    for (int i = 0; i < 2; i++) {
#pragma unroll
        for (int j = 0; j < 4; j++)
            wmma::store_matrix_sync(sc + j*16, acc[i][j], ELD, wmma::mem_row_major);
        __syncwarp();
        int row0 = bm + wm*32 + i*16;
        int col0 = bn + wn*64;
#pragma unroll
        for (int e = lane; e < 256; e += 32) {   // 16 rows x 16 float4
            int r = e >> 4, c4 = (e & 15) * 4;
            float4 o = *reinterpret_cast<float4*>(&sc[r*ELD + c4]);
            if (BIAS) {
                float4 bb = *reinterpret_cast<const float4*>(&bias[col0 + c4]);
                o.x += bb.x; o.y += bb.y; o.z += bb.z; o.w += bb.w;
            }
            if (GELU) {
                o.x = gelu_tanh(o.x); o.y = gelu_tanh(o.y);
                o.z = gelu_tanh(o.z); o.w = gelu_tanh(o.w);
            }
            size_t off = (size_t)(row0 + r)*N + col0 + c4;
            if (RES) {
                float4 r4 = *reinterpret_cast<const float4*>(&Rs[off]);
                o.x += r4.x; o.y += r4.y; o.z += r4.z; o.w += r4.w;
            }
            *reinterpret_cast<float4*>(&C[off]) = o;
        }
        __syncwarp();
    }
}

// ---------------------------------------------------------------------------
// Fused attention per (b, head)
// ---------------------------------------------------------------------------
__global__ void attn_kernel() {
    int bh = blockIdx.x;
    int b = bh >> 1, h = bh & 1;
    __shared__ float sc[SEQ*SEQ];
    __shared__ float qs[SEQ][65];
    __shared__ float ks[SEQ][65];
    int tid = threadIdx.x;

    const float* qbase = g_q + ((size_t)b*SEQ)*DM + h*HDIM;
    const float* kbase = g_k + ((size_t)b*SEQ)*DM + h*HDIM;
    const float* vbase = g_v + ((size_t)b*SEQ)*DM + h*HDIM;

    float acc[5] = {0.f,0.f,0.f,0.f,0.f};
    int qi[5], ki[5];
#pragma unroll
    for (int j = 0; j < 5; j++) {
        int p = tid + j*512; if (p > 2400) p = 2400;
        qi[j] = p / SEQ; ki[j] = p % SEQ;
    }
    for (int c0 = 0; c0 < HDIM; c0 += 64) {
        for (int e = tid; e < SEQ*64; e += 512) {
            int r = e >> 6, c = e & 63;
            qs[r][c] = qbase[(size_t)r*DM + c0 + c];
            ks[r][c] = kbase[(size_t)r*DM + c0 + c];
        }
        __syncthreads();
#pragma unroll 4
        for (int c = 0; c < 64; c++) {
#pragma unroll
            for (int j = 0; j < 5; j++)
                acc[j] += qs[qi[j]][c] * ks[ki[j]][c];
        }
        __syncthreads();
    }
    const float scale = 0.044194173824159216f;
#pragma unroll
    for (int j = 0; j < 5; j++) {
        int p = tid + j*512;
        if (p < SEQ*SEQ) sc[p] = acc[j] * scale;
    }
    __syncthreads();

    if (tid < SEQ) {
        float m = -1e30f;
        for (int k = 0; k < SEQ; k++) m = fmaxf(m, sc[tid*SEQ + k]);
        float ssum = 0.f;
        for (int k = 0; k < SEQ; k++) {
            float e = expf(sc[tid*SEQ + k] - m);
            sc[tid*SEQ + k] = e; ssum += e;
        }
        float inv = 1.f / ssum;
        for (int k = 0; k < SEQ; k++) sc[tid*SEQ + k] *= inv;
    }
    __syncthreads();

    {
        float a[SEQ];
#pragma unroll
        for (int q = 0; q < SEQ; q++) a[q] = 0.f;
        for (int k = 0; k < SEQ; k++) {
            float vv = vbase[(size_t)k*DM + tid];
#pragma unroll
            for (int q = 0; q < SEQ; q++)
                a[q] += sc[q*SEQ + k] * vv;
        }
        float* cb = g_ctx + ((size_t)b*SEQ)*DM + h*HDIM + tid;
#pragma unroll
        for (int q = 0; q < SEQ; q++)
            cb[(size_t)q*DM] = a[q];
    }
}

// ---------------------------------------------------------------------------
// Head GEMM (TF32 WMMA): g_acc[256,1024] += hn[256,50176] @ W[50176,1024]
// BM=256 (full M -> W streamed from DRAM exactly once), BN=64, BK=16,
// split-K = 28 chunks of 1792, atomicAdd reduction.
// 8 warps in 4x2; warp tile 64x32 = 4x2 wmma tiles.
// Single-buffered STATIC smem (24.8 KB); register prefetch overlaps DRAM.
// ---------------------------------------------------------------------------
#define HALD 20
#define HBLD 68
#define HASZ (256*HALD)   // 5120
#define HBSZ (16*HBLD)    // 1088
#define HELD 36

__global__ void __launch_bounds__(256) head_tc(const float* __restrict__ W) {
    __shared__ __align__(32) float hsm[HASZ + HBSZ];   // 24832 B
    float* As = hsm;
    float* Bs = hsm + HASZ;

    int bn = blockIdx.x * 64;
    int kbase = blockIdx.y * 1792;
    int tid = threadIdx.x;
    int warp = tid >> 5, lane = tid & 31;
    int wm = warp & 3;    // rows wm*64
    int wn = warp >> 2;   // cols wn*32

    wmma::fragment<wmma::accumulator,16,16,8,float> acc[4][2];
#pragma unroll
    for (int i = 0; i < 4; i++)
#pragma unroll
        for (int j = 0; j < 2; j++) wmma::fill_fragment(acc[i][j], 0.f);

    float4 ra[4], rb;

    auto loadAB = [&](int k0) {
#pragma unroll
        for (int i = 0; i < 4; i++) {
            int e = tid + i*256;
            int row = e >> 2, c4 = (e & 3) * 4;
            ra[i] = *reinterpret_cast<const float4*>(&g_hn[(size_t)row*KTOT + k0 + c4]);
        }
        {
            int row = tid >> 4, c4 = (tid & 15) * 4;
            rb = *reinterpret_cast<const float4*>(&W[(size_t)(k0+row)*DM + bn + c4]);
        }
    };
    auto stage = [&]() {
#pragma unroll
        for (int i = 0; i < 4; i++) {
            int e = tid + i*256;
            int row = e >> 2, c4 = (e & 3) * 4;
            float* p = &As[row*HALD + c4];
            p[0]=to_tf32(ra[i].x); p[1]=to_tf32(ra[i].y);
            p[2]=to_tf32(ra[i].z); p[3]=to_tf32(ra[i].w);
        }
        {
            int row = tid >> 4, c4 = (tid & 15) * 4;
            float* p = &Bs[row*HBLD + c4];
            p[0]=to_tf32(rb.x); p[1]=to_tf32(rb.y);
            p[2]=to_tf32(rb.z); p[3]=to_tf32(rb.w);
        }
    };

    loadAB(kbase);
    stage();
    __syncthreads();

#pragma unroll 1
    for (int t = 0; t < 112; t++) {
        if (t < 111) loadAB(kbase + (t+1)*16);   // prefetch into regs
        {
#pragma unroll
            for (int ks = 0; ks < 2; ks++) {
                wmma::fragment<wmma::matrix_a,16,16,8,wmma::precision::tf32,wmma::row_major> fa[4];
                wmma::fragment<wmma::matrix_b,16,16,8,wmma::precision::tf32,wmma::row_major> fb[2];
#pragma unroll
                for (int i = 0; i < 4; i++)
                    wmma::load_matrix_sync(fa[i], &As[(wm*64 + i*16)*HALD + ks*8], HALD);
#pragma unroll
                for (int j = 0; j < 2; j++)
                    wmma::load_matrix_sync(fb[j], &Bs[(ks*8)*HBLD + wn*32 + j*16], HBLD);
#pragma unroll
                for (int i = 0; i < 4; i++)
#pragma unroll
                    for (int j = 0; j < 2; j++)
                        wmma::mma_sync(acc[i][j], fa[i], fb[j], acc[i][j]);
            }
        }
        __syncthreads();          // all warps done reading smem
        if (t < 111) {
            stage();
            __syncthreads();
        }
    }

    float* sc = hsm + warp * (16*HELD);   // 8*576 = 4608 floats <= 6208
#pragma unroll 1
    for (int i = 0; i < 4; i++) {
#pragma unroll
        for (int j = 0; j < 2; j++)
            wmma::store_matrix_sync(sc + j*16, acc[i][j], HELD, wmma::mem_row_major);
        __syncwarp();
        int row0 = wm*64 + i*16;
        int col0 = bn + wn*32;
#pragma unroll
        for (int e = lane; e < 512; e += 32) {
            int r = e >> 5, c = e & 31;
            atomicAdd(&g_acc[(size_t)(row0 + r)*DM + col0 + c], sc[r*HELD + c]);
        }
        __syncwarp();
    }
}

__global__ void zero_acc_kernel() {
    g_acc[blockIdx.x*256 + threadIdx.x] = 0.f;
}

__global__ void head_fin_kernel(const float* __restrict__ hb, float* __restrict__ out) {
    int i = blockIdx.x*256 + threadIdx.x;
    float v = g_acc[i] + hb[i & (DM-1)];
    out[i] = v > 0.f ? v : 0.f;
}

// ---------------------------------------------------------------------------
// Launch
// ---------------------------------------------------------------------------
extern "C" void kernel_launch(void* const* d_in, const int* in_sizes, int n_in,
                              void* d_out, int out_size) {
    const float* x     = (const float*)d_in[0];
    const float* pos   = (const float*)d_in[1];
    const float* ln1_s = (const float*)d_in[2];
    const float* ln1_b = (const float*)d_in[3];
    const float* wq    = (const float*)d_in[4];
    const float* wk    = (const float*)d_in[5];
    const float* wv    = (const float*)d_in[6];
    const float* wo    = (const float*)d_in[7];
    const float* ln2_s = (const float*)d_in[8];
    const float* ln2_b = (const float*)d_in[9];
    const float* w1    = (const float*)d_in[10];
    const float* b1    = (const float*)d_in[11];
    const float* w2    = (const float*)d_in[12];
    const float* b2    = (const float*)d_in[13];
    const float* lnf_s = (const float*)d_in[14];
    const float* lnf_b = (const float*)d_in[15];
    const float* hw    = (const float*)d_in[16];
    const float* hb    = (const float*)d_in[17];
    float* out = (float*)d_out;

    float *h, *hn, *q, *k, *v, *ctx, *t;
    cudaGetSymbolAddress((void**)&h,   g_h);
    cudaGetSymbolAddress((void**)&hn,  g_hn);
    cudaGetSymbolAddress((void**)&q,   g_q);
    cudaGetSymbolAddress((void**)&k,   g_k);
    cudaGetSymbolAddress((void**)&v,   g_v);
    cudaGetSymbolAddress((void**)&ctx, g_ctx);
    cudaGetSymbolAddress((void**)&t,   g_t);

    embed_kernel<<<dim3(32, 2, BATCH), dim3(32, 32)>>>(x, pos);

    dim3 gg(DM/128, NTOK/128);   // (8, 98)
    for (int i = 0; i < 2; i++) {
        size_t wofs = (size_t)i*DM*DM;
        ln_kernel<<<NTOK, 256>>>(h, hn, ln1_s + i*DM, ln1_b + i*DM);
        gemm_tc<false,false,false><<<gg, 256>>>(hn, wq + wofs, nullptr, nullptr, q, NTOK, DM, DM);
        gemm_tc<false,false,false><<<gg, 256>>>(hn, wk + wofs, nullptr, nullptr, k, NTOK, DM, DM);
        gemm_tc<false,false,false><<<gg, 256>>>(hn, wv + wofs, nullptr, nullptr, v, NTOK, DM, DM);
        attn_kernel<<<BATCH*NHEAD, 512>>>();
        gemm_tc<true,false,false><<<gg, 256>>>(ctx, wo + wofs, h, nullptr, h, NTOK, DM, DM);
        ln_kernel<<<NTOK, 256>>>(h, hn, ln2_s + i*DM, ln2_b + i*DM);
        gemm_tc<false,true,true><<<gg, 256>>>(hn, w1 + wofs, nullptr, b1 + i*DM, t, NTOK, DM, DM);
        gemm_tc<true,true,false><<<gg, 256>>>(t, w2 + wofs, h, b2 + i*DM, h, NTOK, DM, DM);
    }
    ln_kernel<<<NTOK, 256>>>(h, hn, lnf_s, lnf_b);

    zero_acc_kernel<<<BATCH*DM/256, 256>>>();
    head_tc<<<dim3(DM/64, 28), 256>>>(hw);
    head_fin_kernel<<<BATCH*DM/256, 256>>>(hb, out);
}

// round 6
// speedup vs baseline: 1.5563x; 1.0636x over previous
// Resubmit of Round-5 kernel (bench infra failed twice with no diagnostics;
// source audited: cp.async alignment, group pairing, smem limits all OK).
#include <cuda_runtime.h>
#include <mma.h>
#include <math.h>
#include <stdint.h>

using namespace nvcuda;

#define BATCH 256
#define SEQ   49
#define NTOK  (BATCH*SEQ)      // 12544
#define DM    1024
#define HDIM  512
#define NHEAD 2
#define KTOT  (SEQ*DM)         // 50176
#define EPS   1e-5f

// Scratch (static device globals; allocation APIs are forbidden)
__device__ float g_h  [NTOK*DM];
__device__ float g_hn [NTOK*DM];
__device__ float g_q  [NTOK*DM];
__device__ float g_k  [NTOK*DM];
__device__ float g_v  [NTOK*DM];
__device__ float g_ctx[NTOK*DM];
__device__ float g_t  [NTOK*DM];
__device__ float g_acc[BATCH*DM];

// 16-byte async copy GMEM -> SMEM
__device__ __forceinline__ void cp16(float* s, const float* g) {
    uint32_t sa = (uint32_t)__cvta_generic_to_shared(s);
    asm volatile("cp.async.cg.shared.global [%0], [%1], 16;" :: "r"(sa), "l"(g));
}
__device__ __forceinline__ void cp_commit() {
    asm volatile("cp.async.commit_group;");
}
__device__ __forceinline__ void cp_wait0() {
    asm volatile("cp.async.wait_group 0;");
}

// ---------------------------------------------------------------------------
// Embed: h[b,s,d] = x[b,d,s] + pos[s,d]
// ---------------------------------------------------------------------------
__global__ void embed_kernel(const float* __restrict__ x,
                             const float* __restrict__ pos) {
    __shared__ float tile[32][33];
    int b  = blockIdx.z;
    int s0 = blockIdx.y * 32;
    int d0 = blockIdx.x * 32;
    int tx = threadIdx.x, ty = threadIdx.y;

    if (s0 + tx < SEQ)
        tile[ty][tx] = x[(size_t)b*DM*SEQ + (size_t)(d0+ty)*SEQ + (s0+tx)];
    __syncthreads();
    int ss = s0 + ty, dd = d0 + tx;
    if (ss < SEQ)
        g_h[((size_t)b*SEQ + ss)*DM + dd] = tile[tx][ty] + pos[(size_t)ss*DM + dd];
}

// ---------------------------------------------------------------------------
// LayerNorm per row of 1024
// ---------------------------------------------------------------------------
__global__ void ln_kernel(const float* __restrict__ in, float* __restrict__ out,
                          const float* __restrict__ sc, const float* __restrict__ bi) {
    int r = blockIdx.x;
    const float* row = in + (size_t)r*DM;
    float v[4];
    float s = 0.f, sq = 0.f;
#pragma unroll
    for (int i = 0; i < 4; i++) {
        v[i] = row[threadIdx.x + i*256];
        s += v[i]; sq += v[i]*v[i];
    }
#pragma unroll
    for (int o = 16; o > 0; o >>= 1) {
        s  += __shfl_xor_sync(0xffffffffu, s,  o);
        sq += __shfl_xor_sync(0xffffffffu, sq, o);
    }
    __shared__ float sh[2][8];
    int w = threadIdx.x >> 5, l = threadIdx.x & 31;
    if (l == 0) { sh[0][w] = s; sh[1][w] = sq; }
    __syncthreads();
    s = 0.f; sq = 0.f;
#pragma unroll
    for (int i = 0; i < 8; i++) { s += sh[0][i]; sq += sh[1][i]; }
    float mean = s * (1.f/1024.f);
    float var  = sq * (1.f/1024.f) - mean*mean;
    float rstd = rsqrtf(var + EPS);
#pragma unroll
    for (int i = 0; i < 4; i++) {
        int d = threadIdx.x + i*256;
        out[(size_t)r*DM + d] = (v[i] - mean) * rstd * sc[d] + bi[d];
    }
}

__device__ __forceinline__ float gelu_tanh(float x) {
    float x3 = x*x*x;
    return 0.5f * x * (1.f + tanhf(0.7978845608028654f * (x + 0.044715f*x3)));
}

// ---------------------------------------------------------------------------
// TF32 WMMA GEMM core: C = epi(A[:,K] @ B[K,N]) for one 128x128 tile.
// 256 threads = 8 warps in 4x2; warp tile 32x64 = 2x4 wmma(16x16x8).
// 2-stage cp.async pipeline.  fp32 regs fed straight to HMMA.TF32
// (hardware reads the tf32 bit-subset; no explicit cvt).
// ---------------------------------------------------------------------------
#define ALD 20    // 128x16 A tile, row pitch 20 floats (80B, 16B-aligned)
#define BLD 132   // 16x128 B tile, row pitch 132 floats (528B, 16B-aligned)
#define ASZ (128*ALD)   // 2560
#define BSZ (16*BLD)    // 2112
#define ELD 68          // epilogue scratch pitch
#define GSM (2*ASZ + 2*BSZ)   // 9344 floats = 37376 B

template<bool RES, bool BIAS, bool GELU>
__device__ __forceinline__ void gemm_core(
        const float* __restrict__ A, const float* __restrict__ Bw,
        const float* __restrict__ Rs, const float* __restrict__ bias,
        float* __restrict__ C, int N, int K, int bm, int bn, float* sm) {
    float* AsBase = sm;
    float* BsBase = sm + 2*ASZ;

    int tid = threadIdx.x;
    int warp = tid >> 5, lane = tid & 31;
    int wm = warp & 3;    // rows wm*32
    int wn = warp >> 2;   // cols wn*64

    wmma::fragment<wmma::accumulator,16,16,8,float> acc[2][4];
#pragma unroll
    for (int i = 0; i < 2; i++)
#pragma unroll
        for (int j = 0; j < 4; j++) wmma::fill_fragment(acc[i][j], 0.f);

    auto stage = [&](int buf, int k0) {
        float* As = AsBase + buf*ASZ;
        float* Bs = BsBase + buf*BSZ;
#pragma unroll
        for (int i = 0; i < 2; i++) {
            int e = tid + i*256;
            int r = e >> 2, c4 = (e & 3) * 4;
            cp16(&As[r*ALD + c4], &A[(size_t)(bm + r)*K + k0 + c4]);
        }
#pragma unroll
        for (int i = 0; i < 2; i++) {
            int e = tid + i*256;
            int r = e >> 5, c4 = (e & 31) * 4;
            cp16(&Bs[r*BLD + c4], &Bw[(size_t)(k0 + r)*N + bn + c4]);
        }
    };

    stage(0, 0);
    cp_commit();

    int buf = 0;
    int T = K >> 4;
#pragma unroll 1
    for (int t = 0; t < T; t++) {
        cp_wait0();
        __syncthreads();
        if (t + 1 < T) { stage(buf ^ 1, (t+1) << 4); cp_commit(); }
        float* As = AsBase + buf*ASZ;
        float* Bs = BsBase + buf*BSZ;
#pragma unroll
        for (int ks = 0; ks < 2; ks++) {
            wmma::fragment<wmma::matrix_a,16,16,8,wmma::precision::tf32,wmma::row_major> fa[2];
            wmma::fragment<wmma::matrix_b,16,16,8,wmma::precision::tf32,wmma::row_major> fb[4];
#pragma unroll
            for (int i = 0; i < 2; i++)
                wmma::load_matrix_sync(fa[i], &As[(wm*32 + i*16)*ALD + ks*8], ALD);
#pragma unroll
            for (int j = 0; j < 4; j++)
                wmma::load_matrix_sync(fb[j], &Bs[(ks*8)*BLD + wn*64 + j*16], BLD);
#pragma unroll
            for (int i = 0; i < 2; i++)
#pragma unroll
                for (int j = 0; j < 4; j++)
                    wmma::mma_sync(acc[i][j], fa[i], fb[j], acc[i][j]);
        }
        buf ^= 1;
    }
    __syncthreads();   // before smem reuse as epilogue scratch

    float* sc = sm + warp * (16*ELD);   // 8 warps * 1088 floats = 8704 <= 9344
#pragma unroll 1
    for (int i = 0; i < 2; i++) {
#pragma unroll
        for (int j = 0; j < 4; j++)
            wmma::store_matrix_sync(sc + j*16, acc[i][j], ELD, wmma::mem_row_major);
        __syncwarp();
        int row0 = bm + wm*32 + i*16;
        int col0 = bn + wn*64;
#pragma unroll
        for (int e = lane; e < 256; e += 32) {   // 16 rows x 16 float4
            int r = e >> 4, c4 = (e & 15) * 4;
            float4 o = *reinterpret_cast<float4*>(&sc[r*ELD + c4]);
            if (BIAS) {
                float4 bb = *reinterpret_cast<const float4*>(&bias[col0 + c4]);
                o.x += bb.x; o.y += bb.y; o.z += bb.z; o.w += bb.w;
            }
            if (GELU) {
                o.x = gelu_tanh(o.x); o.y = gelu_tanh(o.y);
                o.z = gelu_tanh(o.z); o.w = gelu_tanh(o.w);
            }
            size_t off = (size_t)(row0 + r)*N + col0 + c4;
            if (RES) {
                float4 r4 = *reinterpret_cast<const float4*>(&Rs[off]);
                o.x += r4.x; o.y += r4.y; o.z += r4.z; o.w += r4.w;
            }
            *reinterpret_cast<float4*>(&C[off]) = o;
        }
        __syncwarp();
    }
}

template<bool RES, bool BIAS, bool GELU>
__global__ void __launch_bounds__(256) gemm_tc(
        const float* __restrict__ A, const float* __restrict__ Bw,
        const float* __restrict__ Rs, const float* __restrict__ bias,
        float* __restrict__ C, int N, int K) {
    __shared__ __align__(16) float sm[GSM];
    gemm_core<RES,BIAS,GELU>(A, Bw, Rs, bias, C, N, K,
                             blockIdx.y*128, blockIdx.x*128, sm);
}

// QKV fused: blockIdx.x in [0,24): sel = x>>3 picks (B,C) pair, (x&7) picks bn.
__global__ void __launch_bounds__(256) gemm_qkv(
        const float* __restrict__ A,
        const float* __restrict__ B0, const float* __restrict__ B1,
        const float* __restrict__ B2,
        float* __restrict__ C0, float* __restrict__ C1, float* __restrict__ C2) {
    __shared__ __align__(16) float sm[GSM];
    int sel = blockIdx.x >> 3;
    const float* Bw = (sel == 0) ? B0 : (sel == 1) ? B1 : B2;
    float*       C  = (sel == 0) ? C0 : (sel == 1) ? C1 : C2;
    gemm_core<false,false,false>(A, Bw, nullptr, nullptr, C, DM, DM,
                                 blockIdx.y*128, (blockIdx.x & 7)*128, sm);
}

// ---------------------------------------------------------------------------
// Fused attention per (b, head)
// ---------------------------------------------------------------------------
__global__ void attn_kernel() {
    int bh = blockIdx.x;
    int b = bh >> 1, h = bh & 1;
    __shared__ float sc[SEQ*SEQ];
    __shared__ float qs[SEQ][65];
    __shared__ float ks[SEQ][65];
    int tid = threadIdx.x;

    const float* qbase = g_q + ((size_t)b*SEQ)*DM + h*HDIM;
    const float* kbase = g_k + ((size_t)b*SEQ)*DM + h*HDIM;
    const float* vbase = g_v + ((size_t)b*SEQ)*DM + h*HDIM;

    float acc[5] = {0.f,0.f,0.f,0.f,0.f};
    int qi[5], ki[5];
#pragma unroll
    for (int j = 0; j < 5; j++) {
        int p = tid + j*512; if (p > 2400) p = 2400;
        qi[j] = p / SEQ; ki[j] = p % SEQ;
    }
    for (int c0 = 0; c0 < HDIM; c0 += 64) {
        for (int e = tid; e < SEQ*64; e += 512) {
            int r = e >> 6, c = e & 63;
            qs[r][c] = qbase[(size_t)r*DM + c0 + c];
            ks[r][c] = kbase[(size_t)r*DM + c0 + c];
        }
        __syncthreads();
#pragma unroll 4
        for (int c = 0; c < 64; c++) {
#pragma unroll
            for (int j = 0; j < 5; j++)
                acc[j] += qs[qi[j]][c] * ks[ki[j]][c];
        }
        __syncthreads();
    }
    const float scale = 0.044194173824159216f;
#pragma unroll
    for (int j = 0; j < 5; j++) {
        int p = tid + j*512;
        if (p < SEQ*SEQ) sc[p] = acc[j] * scale;
    }
    __syncthreads();

    if (tid < SEQ) {
        float m = -1e30f;
        for (int k = 0; k < SEQ; k++) m = fmaxf(m, sc[tid*SEQ + k]);
        float ssum = 0.f;
        for (int k = 0; k < SEQ; k++) {
            float e = expf(sc[tid*SEQ + k] - m);
            sc[tid*SEQ + k] = e; ssum += e;
        }
        float inv = 1.f / ssum;
        for (int k = 0; k < SEQ; k++) sc[tid*SEQ + k] *= inv;
    }
    __syncthreads();

    {
        float a[SEQ];
#pragma unroll
        for (int q = 0; q < SEQ; q++) a[q] = 0.f;
        for (int k = 0; k < SEQ; k++) {
            float vv = vbase[(size_t)k*DM + tid];
#pragma unroll
            for (int q = 0; q < SEQ; q++)
                a[q] += sc[q*SEQ + k] * vv;
        }
        float* cb = g_ctx + ((size_t)b*SEQ)*DM + h*HDIM + tid;
#pragma unroll
        for (int q = 0; q < SEQ; q++)
            cb[(size_t)q*DM] = a[q];
    }
}

// ---------------------------------------------------------------------------
// Head GEMM (TF32 WMMA): g_acc[256,1024] += hn[256,50176] @ W[50176,1024]
// BM=256 (full M -> W streams from DRAM exactly once), BN=64, BK=16,
// split-K = 28 chunks of 1792, atomicAdd reduction.
// 2-stage cp.async pipeline, 8 warps in 4x2; warp tile 64x32.
// ---------------------------------------------------------------------------
#define HALD 16           // no padding (cp.async alignment); DRAM-bound anyway
#define HBLD 68
#define HASZ (256*HALD)   // 4096
#define HBSZ (16*HBLD)    // 1088
#define HELD 36
#define HSM  (2*HASZ + 2*HBSZ)   // 10368 floats = 41472 B

__global__ void __launch_bounds__(256) head_tc(const float* __restrict__ W) {
    __shared__ __align__(16) float hsm[HSM];
    float* AsBase = hsm;
    float* BsBase = hsm + 2*HASZ;

    int bn = blockIdx.x * 64;
    int kbase = blockIdx.y * 1792;
    int tid = threadIdx.x;
    int warp = tid >> 5, lane = tid & 31;
    int wm = warp & 3;    // rows wm*64
    int wn = warp >> 2;   // cols wn*32

    wmma::fragment<wmma::accumulator,16,16,8,float> acc[4][2];
#pragma unroll
    for (int i = 0; i < 4; i++)
#pragma unroll
        for (int j = 0; j < 2; j++) wmma::fill_fragment(acc[i][j], 0.f);

    auto stage = [&](int buf, int k0) {
        float* As = AsBase + buf*HASZ;
        float* Bs = BsBase + buf*HBSZ;
#pragma unroll
        for (int i = 0; i < 4; i++) {
            int e = tid + i*256;
            int r = e >> 2, c4 = (e & 3) * 4;
            cp16(&As[r*HALD + c4], &g_hn[(size_t)r*KTOT + k0 + c4]);
        }
        {
            int r = tid >> 4, c4 = (tid & 15) * 4;
            cp16(&Bs[r*HBLD + c4], &W[(size_t)(k0 + r)*DM + bn + c4]);
        }
    };

    stage(0, kbase);
    cp_commit();

    int buf = 0;
#pragma unroll 1
    for (int t = 0; t < 112; t++) {
        cp_wait0();
        __syncthreads();
        if (t < 111) { stage(buf ^ 1, kbase + (t+1)*16); cp_commit(); }
        float* As = AsBase + buf*HASZ;
        float* Bs = BsBase + buf*HBSZ;
#pragma unroll
        for (int ks = 0; ks < 2; ks++) {
            wmma::fragment<wmma::matrix_a,16,16,8,wmma::precision::tf32,wmma::row_major> fa[4];
            wmma::fragment<wmma::matrix_b,16,16,8,wmma::precision::tf32,wmma::row_major> fb[2];
#pragma unroll
            for (int i = 0; i < 4; i++)
                wmma::load_matrix_sync(fa[i], &As[(wm*64 + i*16)*HALD + ks*8], HALD);
#pragma unroll
            for (int j = 0; j < 2; j++)
                wmma::load_matrix_sync(fb[j], &Bs[(ks*8)*HBLD + wn*32 + j*16], HBLD);
#pragma unroll
            for (int i = 0; i < 4; i++)
#pragma unroll
                for (int j = 0; j < 2; j++)
                    wmma::mma_sync(acc[i][j], fa[i], fb[j], acc[i][j]);
        }
        buf ^= 1;
    }
    __syncthreads();   // before smem reuse

    float* sc = hsm + warp * (16*HELD);   // 8*576 = 4608 floats <= 10368
#pragma unroll 1
    for (int i = 0; i < 4; i++) {
#pragma unroll
        for (int j = 0; j < 2; j++)
            wmma::store_matrix_sync(sc + j*16, acc[i][j], HELD, wmma::mem_row_major);
        __syncwarp();
        int row0 = wm*64 + i*16;
        int col0 = bn + wn*32;
#pragma unroll
        for (int e = lane; e < 512; e += 32) {
            int r = e >> 5, c = e & 31;
            atomicAdd(&g_acc[(size_t)(row0 + r)*DM + col0 + c], sc[r*HELD + c]);
        }
        __syncwarp();
    }
}

__global__ void zero_acc_kernel() {
    g_acc[blockIdx.x*256 + threadIdx.x] = 0.f;
}

__global__ void head_fin_kernel(const float* __restrict__ hb, float* __restrict__ out) {
    int i = blockIdx.x*256 + threadIdx.x;
    float v = g_acc[i] + hb[i & (DM-1)];
    out[i] = v > 0.f ? v : 0.f;
}

// ---------------------------------------------------------------------------
// Launch
// ---------------------------------------------------------------------------
extern "C" void kernel_launch(void* const* d_in, const int* in_sizes, int n_in,
                              void* d_out, int out_size) {
    const float* x     = (const float*)d_in[0];
    const float* pos   = (const float*)d_in[1];
    const float* ln1_s = (const float*)d_in[2];
    const float* ln1_b = (const float*)d_in[3];
    const float* wq    = (const float*)d_in[4];
    const float* wk    = (const float*)d_in[5];
    const float* wv    = (const float*)d_in[6];
    const float* wo    = (const float*)d_in[7];
    const float* ln2_s = (const float*)d_in[8];
    const float* ln2_b = (const float*)d_in[9];
    const float* w1    = (const float*)d_in[10];
    const float* b1    = (const float*)d_in[11];
    const float* w2    = (const float*)d_in[12];
    const float* b2    = (const float*)d_in[13];
    const float* lnf_s = (const float*)d_in[14];
    const float* lnf_b = (const float*)d_in[15];
    const float* hw    = (const float*)d_in[16];
    const float* hb    = (const float*)d_in[17];
    float* out = (float*)d_out;

    float *h, *hn, *q, *k, *v, *ctx, *t;
    cudaGetSymbolAddress((void**)&h,   g_h);
    cudaGetSymbolAddress((void**)&hn,  g_hn);
    cudaGetSymbolAddress((void**)&q,   g_q);
    cudaGetSymbolAddress((void**)&k,   g_k);
    cudaGetSymbolAddress((void**)&v,   g_v);
    cudaGetSymbolAddress((void**)&ctx, g_ctx);
    cudaGetSymbolAddress((void**)&t,   g_t);

    embed_kernel<<<dim3(32, 2, BATCH), dim3(32, 32)>>>(x, pos);

    dim3 gg(DM/128, NTOK/128);    // (8, 98)
    dim3 gq(3*DM/128, NTOK/128);  // (24, 98)
    for (int i = 0; i < 2; i++) {
        size_t wofs = (size_t)i*DM*DM;
        ln_kernel<<<NTOK, 256>>>(h, hn, ln1_s + i*DM, ln1_b + i*DM);
        gemm_qkv<<<gq, 256>>>(hn, wq + wofs, wk + wofs, wv + wofs, q, k, v);
        attn_kernel<<<BATCH*NHEAD, 512>>>();
        gemm_tc<true,false,false><<<gg, 256>>>(ctx, wo + wofs, h, nullptr, h, DM, DM);
        ln_kernel<<<NTOK, 256>>>(h, hn, ln2_s + i*DM, ln2_b + i*DM);
        gemm_tc<false,true,true><<<gg, 256>>>(hn, w1 + wofs, nullptr, b1 + i*DM, t, DM, DM);
        gemm_tc<true,true,false><<<gg, 256>>>(t, w2 + wofs, h, b2 + i*DM, h, DM, DM);
    }
    ln_kernel<<<NTOK, 256>>>(h, hn, lnf_s, lnf_b);

    zero_acc_kernel<<<BATCH*DM/256, 256>>>();
    head_tc<<<dim3(DM/64, 28), 256>>>(hw);
    head_fin_kernel<<<BATCH*DM/256, 256>>>(hb, out);
}

// round 7
// speedup vs baseline: 1.6209x; 1.0415x over previous
#include <cuda_runtime.h>
#include <mma.h>
#include <math.h>
#include <stdint.h>

using namespace nvcuda;

#define BATCH 256
#define SEQ   49
#define NTOK  (BATCH*SEQ)      // 12544
#define DM    1024
#define HDIM  512
#define NHEAD 2
#define KTOT  (SEQ*DM)         // 50176
#define EPS   1e-5f

// Scratch (static device globals; allocation APIs are forbidden)
__device__ float g_h  [NTOK*DM];
__device__ float g_hn [NTOK*DM];
__device__ float g_q  [NTOK*DM];
__device__ float g_k  [NTOK*DM];
__device__ float g_v  [NTOK*DM];
__device__ float g_ctx[NTOK*DM];
__device__ float g_t  [NTOK*DM];
__device__ float g_acc[BATCH*DM];

__device__ __forceinline__ float to_tf32(float x) {
    uint32_t r;
    asm("cvt.rna.tf32.f32 %0, %1;" : "=r"(r) : "f"(x));
    return __uint_as_float(r);
}

// 16-byte async copy GMEM -> SMEM
__device__ __forceinline__ void cp16(float* s, const float* g) {
    uint32_t sa = (uint32_t)__cvta_generic_to_shared(s);
    asm volatile("cp.async.cg.shared.global [%0], [%1], 16;" :: "r"(sa), "l"(g));
}
__device__ __forceinline__ void cp_commit() {
    asm volatile("cp.async.commit_group;");
}
__device__ __forceinline__ void cp_wait1() {
    asm volatile("cp.async.wait_group 1;");
}
__device__ __forceinline__ void cp_wait0() {
    asm volatile("cp.async.wait_group 0;");
}

// ---------------------------------------------------------------------------
// Embed: h[b,s,d] = x[b,d,s] + pos[s,d]
// ---------------------------------------------------------------------------
__global__ void embed_kernel(const float* __restrict__ x,
                             const float* __restrict__ pos) {
    __shared__ float tile[32][33];
    int b  = blockIdx.z;
    int s0 = blockIdx.y * 32;
    int d0 = blockIdx.x * 32;
    int tx = threadIdx.x, ty = threadIdx.y;

    if (s0 + tx < SEQ)
        tile[ty][tx] = x[(size_t)b*DM*SEQ + (size_t)(d0+ty)*SEQ + (s0+tx)];
    __syncthreads();
    int ss = s0 + ty, dd = d0 + tx;
    if (ss < SEQ)
        g_h[((size_t)b*SEQ + ss)*DM + dd] = tile[tx][ty] + pos[(size_t)ss*DM + dd];
}

// ---------------------------------------------------------------------------
// LayerNorm per row of 1024.  Output rounded to tf32 (feeds GEMMs as A).
// ---------------------------------------------------------------------------
__global__ void ln_kernel(const float* __restrict__ in, float* __restrict__ out,
                          const float* __restrict__ sc, const float* __restrict__ bi) {
    int r = blockIdx.x;
    const float* row = in + (size_t)r*DM;
    float v[4];
    float s = 0.f, sq = 0.f;
#pragma unroll
    for (int i = 0; i < 4; i++) {
        v[i] = row[threadIdx.x + i*256];
        s += v[i]; sq += v[i]*v[i];
    }
#pragma unroll
    for (int o = 16; o > 0; o >>= 1) {
        s  += __shfl_xor_sync(0xffffffffu, s,  o);
        sq += __shfl_xor_sync(0xffffffffu, sq, o);
    }
    __shared__ float sh[2][8];
    int w = threadIdx.x >> 5, l = threadIdx.x & 31;
    if (l == 0) { sh[0][w] = s; sh[1][w] = sq; }
    __syncthreads();
    s = 0.f; sq = 0.f;
#pragma unroll
    for (int i = 0; i < 8; i++) { s += sh[0][i]; sq += sh[1][i]; }
    float mean = s * (1.f/1024.f);
    float var  = sq * (1.f/1024.f) - mean*mean;
    float rstd = rsqrtf(var + EPS);
#pragma unroll
    for (int i = 0; i < 4; i++) {
        int d = threadIdx.x + i*256;
        out[(size_t)r*DM + d] = to_tf32((v[i] - mean) * rstd * sc[d] + bi[d]);
    }
}

__device__ __forceinline__ float gelu_tanh(float x) {
    float x3 = x*x*x;
    return 0.5f * x * (1.f + tanhf(0.7978845608028654f * (x + 0.044715f*x3)));
}

// ---------------------------------------------------------------------------
// TF32 WMMA GEMM core: C = epi(A[:,K] @ B[K,N]) for one 128x64 tile.
// 256 threads = 8 warps in 4x2; warp tile 32x32 = 2x2 wmma(16x16x8).
// 3-stage cp.async pipeline (wait_group 1).
// A comes pre-rounded (rna) from producers; B fragments rounded in-register.
// ---------------------------------------------------------------------------
#define ALD 20          // 128x16 A tile, pitch 20 floats (80B)
#define BLD 68          // 16x64 B tile, pitch 68 floats (272B)
#define ASZ (128*ALD)   // 2560
#define BSZ (16*BLD)    // 1088
#define STG (ASZ+BSZ)   // 3648
#define GSM (3*STG)     // 10944 floats = 43776 B
#define ELD 36          // epilogue scratch pitch

template<bool RES, bool BIAS, bool GELU, bool RND>
__device__ __forceinline__ void gemm_core(
        const float* __restrict__ A, const float* __restrict__ Bw,
        const float* __restrict__ Rs, const float* __restrict__ bias,
        float* __restrict__ C, int N, int K, int bm, int bn, float* sm) {
    int tid = threadIdx.x;
    int warp = tid >> 5, lane = tid & 31;
    int wm = warp & 3;    // rows wm*32
    int wn = warp >> 2;   // cols wn*32

    wmma::fragment<wmma::accumulator,16,16,8,float> acc[2][2];
#pragma unroll
    for (int i = 0; i < 2; i++)
#pragma unroll
        for (int j = 0; j < 2; j++) wmma::fill_fragment(acc[i][j], 0.f);

    auto stage = [&](int buf, int k0) {
        float* As = sm + buf*STG;
        float* Bs = As + ASZ;
#pragma unroll
        for (int i = 0; i < 2; i++) {      // A: 512 cp16, 2/thread
            int e = tid + i*256;
            int r = e >> 2, c4 = (e & 3) * 4;
            cp16(&As[r*ALD + c4], &A[(size_t)(bm + r)*K + k0 + c4]);
        }
        {                                   // B: 256 cp16, 1/thread
            int r = tid >> 4, c4 = (tid & 15) * 4;
            cp16(&Bs[r*BLD + c4], &Bw[(size_t)(k0 + r)*N + bn + c4]);
        }
    };

    int T = K >> 4;
    stage(0, 0);  cp_commit();
    stage(1, 16); cp_commit();

#pragma unroll 1
    for (int t = 0; t < T; t++) {
        cp_wait1();            // buffer t%3 ready (t+1 may still be in flight)
        __syncthreads();
        if (t + 2 < T) { stage((t+2)%3, (t+2) << 4); cp_commit(); }
        float* As = sm + (t%3)*STG;
        float* Bs = As + ASZ;
#pragma unroll
        for (int ks = 0; ks < 2; ks++) {
            wmma::fragment<wmma::matrix_a,16,16,8,wmma::precision::tf32,wmma::row_major> fa[2];
            wmma::fragment<wmma::matrix_b,16,16,8,wmma::precision::tf32,wmma::row_major> fb[2];
#pragma unroll
            for (int i = 0; i < 2; i++)
                wmma::load_matrix_sync(fa[i], &As[(wm*32 + i*16)*ALD + ks*8], ALD);
#pragma unroll
            for (int j = 0; j < 2; j++) {
                wmma::load_matrix_sync(fb[j], &Bs[(ks*8)*BLD + wn*32 + j*16], BLD);
#pragma unroll
                for (int e = 0; e < fb[j].num_elements; e++)
                    fb[j].x[e] = to_tf32(fb[j].x[e]);
            }
#pragma unroll
            for (int i = 0; i < 2; i++)
#pragma unroll
                for (int j = 0; j < 2; j++)
                    wmma::mma_sync(acc[i][j], fa[i], fb[j], acc[i][j]);
        }
        __syncthreads();       // done reading buffer t%3 before it is re-staged
    }

    float* sc = sm + warp * (16*ELD);   // 8 warps * 576 floats = 4608 <= 10944
#pragma unroll 1
    for (int i = 0; i < 2; i++) {
#pragma unroll
        for (int j = 0; j < 2; j++)
            wmma::store_matrix_sync(sc + j*16, acc[i][j], ELD, wmma::mem_row_major);
        __syncwarp();
        int row0 = bm + wm*32 + i*16;
        int col0 = bn + wn*32;
#pragma unroll
        for (int e = lane; e < 128; e += 32) {   // 16 rows x 8 float4
            int r = e >> 3, c4 = (e & 7) * 4;
            float4 o = *reinterpret_cast<float4*>(&sc[r*ELD + c4]);
            if (BIAS) {
                float4 bb = *reinterpret_cast<const float4*>(&bias[col0 + c4]);
                o.x += bb.x; o.y += bb.y; o.z += bb.z; o.w += bb.w;
            }
            if (GELU) {
                o.x = gelu_tanh(o.x); o.y = gelu_tanh(o.y);
                o.z = gelu_tanh(o.z); o.w = gelu_tanh(o.w);
            }
            size_t off = (size_t)(row0 + r)*N + col0 + c4;
            if (RES) {
                float4 r4 = *reinterpret_cast<const float4*>(&Rs[off]);
                o.x += r4.x; o.y += r4.y; o.z += r4.z; o.w += r4.w;
            }
            if (RND) {
                o.x = to_tf32(o.x); o.y = to_tf32(o.y);
                o.z = to_tf32(o.z); o.w = to_tf32(o.w);
            }
            *reinterpret_cast<float4*>(&C[off]) = o;
        }
        __syncwarp();
    }
}

template<bool RES, bool BIAS, bool GELU, bool RND>
__global__ void __launch_bounds__(256) gemm_tc(
        const float* __restrict__ A, const float* __restrict__ Bw,
        const float* __restrict__ Rs, const float* __restrict__ bias,
        float* __restrict__ C, int N, int K) {
    __shared__ __align__(16) float sm[GSM];
    gemm_core<RES,BIAS,GELU,RND>(A, Bw, Rs, bias, C, N, K,
                                 blockIdx.y*128, blockIdx.x*64, sm);
}

// QKV fused: blockIdx.x in [0,48): sel = x>>4 picks (B,C) pair, (x&15) -> bn.
__global__ void __launch_bounds__(256) gemm_qkv(
        const float* __restrict__ A,
        const float* __restrict__ B0, const float* __restrict__ B1,
        const float* __restrict__ B2,
        float* __restrict__ C0, float* __restrict__ C1, float* __restrict__ C2) {
    __shared__ __align__(16) float sm[GSM];
    int sel = blockIdx.x >> 4;
    const float* Bw = (sel == 0) ? B0 : (sel == 1) ? B1 : B2;
    float*       C  = (sel == 0) ? C0 : (sel == 1) ? C1 : C2;
    gemm_core<false,false,false,false>(A, Bw, nullptr, nullptr, C, DM, DM,
                                       blockIdx.y*128, (blockIdx.x & 15)*64, sm);
}

// ---------------------------------------------------------------------------
// Fused attention per (b, head).  512 threads.
// scores: 10 threads share one q-row (q value 1 LDS broadcast per c).
// softmax: warp per row.  ctx: thread per head-dim column.
// ---------------------------------------------------------------------------
__global__ void attn_kernel() {
    int bh = blockIdx.x;
    int b = bh >> 1, h = bh & 1;
    __shared__ float sc[SEQ*SEQ];
    __shared__ float qs[SEQ][65];
    __shared__ float ks[SEQ][65];
    int tid = threadIdx.x;

    const float* qbase = g_q + ((size_t)b*SEQ)*DM + h*HDIM;
    const float* kbase = g_k + ((size_t)b*SEQ)*DM + h*HDIM;
    const float* vbase = g_v + ((size_t)b*SEQ)*DM + h*HDIM;

    // --- scores ---
    int q  = tid / 10;            // 0..51
    int k0 = (tid % 10) * 5;      // 0,5,..,45
    bool act = (q < SEQ);
    int qc = act ? q : SEQ-1;
    float acc5[5] = {0.f,0.f,0.f,0.f,0.f};
    for (int c0 = 0; c0 < HDIM; c0 += 64) {
        for (int e = tid; e < SEQ*64; e += 512) {
            int r = e >> 6, c = e & 63;
            qs[r][c] = qbase[(size_t)r*DM + c0 + c];
            ks[r][c] = kbase[(size_t)r*DM + c0 + c];
        }
        __syncthreads();
#pragma unroll 4
        for (int c = 0; c < 64; c++) {
            float qv = qs[qc][c];
#pragma unroll
            for (int j = 0; j < 5; j++) {
                int kk = k0 + j; if (kk > SEQ-1) kk = SEQ-1;
                acc5[j] += qv * ks[kk][c];
            }
        }
        __syncthreads();
    }
    const float scale = 0.044194173824159216f;
    if (act) {
#pragma unroll
        for (int j = 0; j < 5; j++) {
            int kk = k0 + j;
            if (kk < SEQ) sc[q*SEQ + kk] = acc5[j] * scale;
        }
    }
    __syncthreads();

    // --- softmax: warp per row ---
    {
        int warp = tid >> 5, lane = tid & 31;
        for (int row = warp; row < SEQ; row += 16) {
            float v0 = (lane      < SEQ) ? sc[row*SEQ + lane]      : -1e30f;
            float v1 = (lane + 32 < SEQ) ? sc[row*SEQ + lane + 32] : -1e30f;
            float m = fmaxf(v0, v1);
#pragma unroll
            for (int o = 16; o > 0; o >>= 1)
                m = fmaxf(m, __shfl_xor_sync(0xffffffffu, m, o));
            float e0 = (lane      < SEQ) ? expf(v0 - m) : 0.f;
            float e1 = (lane + 32 < SEQ) ? expf(v1 - m) : 0.f;
            float s = e0 + e1;
#pragma unroll
            for (int o = 16; o > 0; o >>= 1)
                s += __shfl_xor_sync(0xffffffffu, s, o);
            float inv = 1.f / s;
            if (lane      < SEQ) sc[row*SEQ + lane]      = e0 * inv;
            if (lane + 32 < SEQ) sc[row*SEQ + lane + 32] = e1 * inv;
        }
    }
    __syncthreads();

    // --- ctx (output rounded: feeds wo GEMM as A) ---
    {
        float a[SEQ];
#pragma unroll
        for (int qq = 0; qq < SEQ; qq++) a[qq] = 0.f;
        for (int k = 0; k < SEQ; k++) {
            float vv = vbase[(size_t)k*DM + tid];
#pragma unroll
            for (int qq = 0; qq < SEQ; qq++)
                a[qq] += sc[qq*SEQ + k] * vv;
        }
        float* cb = g_ctx + ((size_t)b*SEQ)*DM + h*HDIM + tid;
#pragma unroll
        for (int qq = 0; qq < SEQ; qq++)
            cb[(size_t)qq*DM] = to_tf32(a[qq]);
    }
}

// ---------------------------------------------------------------------------
// Head GEMM (TF32 WMMA): g_acc[256,1024] += hn[256,50176] @ W[50176,1024]
// BM=256 (full M -> W streams from DRAM exactly once), BN=64, BK=16,
// split-K = 28 chunks of 1792, atomicAdd reduction.  2-stage cp.async.
// A (g_hn) pre-rounded; B fragments rounded in-register.
// ---------------------------------------------------------------------------
#define HALD 16
#define HBLD 68
#define HASZ (256*HALD)   // 4096
#define HBSZ (16*HBLD)    // 1088
#define HELD 36
#define HSM  (2*HASZ + 2*HBSZ)   // 10368 floats = 41472 B

__global__ void __launch_bounds__(256) head_tc(const float* __restrict__ W) {
    __shared__ __align__(16) float hsm[HSM];
    float* AsBase = hsm;
    float* BsBase = hsm + 2*HASZ;

    int bn = blockIdx.x * 64;
    int kbase = blockIdx.y * 1792;
    int tid = threadIdx.x;
    int warp = tid >> 5, lane = tid & 31;
    int wm = warp & 3;    // rows wm*64
    int wn = warp >> 2;   // cols wn*32

    wmma::fragment<wmma::accumulator,16,16,8,float> acc[4][2];
#pragma unroll
    for (int i = 0; i < 4; i++)
#pragma unroll
        for (int j = 0; j < 2; j++) wmma::fill_fragment(acc[i][j], 0.f);

    auto stage = [&](int buf, int k0) {
        float* As = AsBase + buf*HASZ;
        float* Bs = BsBase + buf*HBSZ;
#pragma unroll
        for (int i = 0; i < 4; i++) {
            int e = tid + i*256;
            int r = e >> 2, c4 = (e & 3) * 4;
            cp16(&As[r*HALD + c4], &g_hn[(size_t)r*KTOT + k0 + c4]);
        }
        {
            int r = tid >> 4, c4 = (tid & 15) * 4;
            cp16(&Bs[r*HBLD + c4], &W[(size_t)(k0 + r)*DM + bn + c4]);
        }
    };

    stage(0, kbase);
    cp_commit();

    int buf = 0;
#pragma unroll 1
    for (int t = 0; t < 112; t++) {
        cp_wait0();
        __syncthreads();
        if (t < 111) { stage(buf ^ 1, kbase + (t+1)*16); cp_commit(); }
        float* As = AsBase + buf*HASZ;
        float* Bs = BsBase + buf*HBSZ;
#pragma unroll
        for (int ks = 0; ks < 2; ks++) {
            wmma::fragment<wmma::matrix_a,16,16,8,wmma::precision::tf32,wmma::row_major> fa[4];
            wmma::fragment<wmma::matrix_b,16,16,8,wmma::precision::tf32,wmma::row_major> fb[2];
#pragma unroll
            for (int i = 0; i < 4; i++)
                wmma::load_matrix_sync(fa[i], &As[(wm*64 + i*16)*HALD + ks*8], HALD);
#pragma unroll
            for (int j = 0; j < 2; j++) {
                wmma::load_matrix_sync(fb[j], &Bs[(ks*8)*HBLD + wn*32 + j*16], HBLD);
#pragma unroll
                for (int e = 0; e < fb[j].num_elements; e++)
                    fb[j].x[e] = to_tf32(fb[j].x[e]);
            }
#pragma unroll
            for (int i = 0; i < 4; i++)
#pragma unroll
                for (int j = 0; j < 2; j++)
                    wmma::mma_sync(acc[i][j], fa[i], fb[j], acc[i][j]);
        }
        buf ^= 1;
    }
    __syncthreads();   // before smem reuse

    float* sc = hsm + warp * (16*HELD);   // 8*576 = 4608 floats <= 10368
#pragma unroll 1
    for (int i = 0; i < 4; i++) {
#pragma unroll
        for (int j = 0; j < 2; j++)
            wmma::store_matrix_sync(sc + j*16, acc[i][j], HELD, wmma::mem_row_major);
        __syncwarp();
        int row0 = wm*64 + i*16;
        int col0 = bn + wn*32;
#pragma unroll
        for (int e = lane; e < 512; e += 32) {
            int r = e >> 5, c = e & 31;
            atomicAdd(&g_acc[(size_t)(row0 + r)*DM + col0 + c], sc[r*HELD + c]);
        }
        __syncwarp();
    }
}

__global__ void zero_acc_kernel() {
    g_acc[blockIdx.x*256 + threadIdx.x] = 0.f;
}

__global__ void head_fin_kernel(const float* __restrict__ hb, float* __restrict__ out) {
    int i = blockIdx.x*256 + threadIdx.x;
    float v = g_acc[i] + hb[i & (DM-1)];
    out[i] = v > 0.f ? v : 0.f;
}

// ---------------------------------------------------------------------------
// Launch
// ---------------------------------------------------------------------------
extern "C" void kernel_launch(void* const* d_in, const int* in_sizes, int n_in,
                              void* d_out, int out_size) {
    const float* x     = (const float*)d_in[0];
    const float* pos   = (const float*)d_in[1];
    const float* ln1_s = (const float*)d_in[2];
    const float* ln1_b = (const float*)d_in[3];
    const float* wq    = (const float*)d_in[4];
    const float* wk    = (const float*)d_in[5];
    const float* wv    = (const float*)d_in[6];
    const float* wo    = (const float*)d_in[7];
    const float* ln2_s = (const float*)d_in[8];
    const float* ln2_b = (const float*)d_in[9];
    const float* w1    = (const float*)d_in[10];
    const float* b1    = (const float*)d_in[11];
    const float* w2    = (const float*)d_in[12];
    const float* b2    = (const float*)d_in[13];
    const float* lnf_s = (const float*)d_in[14];
    const float* lnf_b = (const float*)d_in[15];
    const float* hw    = (const float*)d_in[16];
    const float* hb    = (const float*)d_in[17];
    float* out = (float*)d_out;

    float *h, *hn, *q, *k, *v, *ctx, *t;
    cudaGetSymbolAddress((void**)&h,   g_h);
    cudaGetSymbolAddress((void**)&hn,  g_hn);
    cudaGetSymbolAddress((void**)&q,   g_q);
    cudaGetSymbolAddress((void**)&k,   g_k);
    cudaGetSymbolAddress((void**)&v,   g_v);
    cudaGetSymbolAddress((void**)&ctx, g_ctx);
    cudaGetSymbolAddress((void**)&t,   g_t);

    embed_kernel<<<dim3(32, 2, BATCH), dim3(32, 32)>>>(x, pos);

    dim3 gg(DM/64, NTOK/128);     // (16, 98)
    dim3 gq(3*DM/64, NTOK/128);   // (48, 98)
    for (int i = 0; i < 2; i++) {
        size_t wofs = (size_t)i*DM*DM;
        ln_kernel<<<NTOK, 256>>>(h, hn, ln1_s + i*DM, ln1_b + i*DM);
        gemm_qkv<<<gq, 256>>>(hn, wq + wofs, wk + wofs, wv + wofs, q, k, v);
        attn_kernel<<<BATCH*NHEAD, 512>>>();
        gemm_tc<true,false,false,false><<<gg, 256>>>(ctx, wo + wofs, h, nullptr, h, DM, DM);
        ln_kernel<<<NTOK, 256>>>(h, hn, ln2_s + i*DM, ln2_b + i*DM);
        gemm_tc<false,true,true,true><<<gg, 256>>>(hn, w1 + wofs, nullptr, b1 + i*DM, t, DM, DM);
        gemm_tc<true,true,false,false><<<gg, 256>>>(t, w2 + wofs, h, b2 + i*DM, h, DM, DM);
    }
    ln_kernel<<<NTOK, 256>>>(h, hn, lnf_s, lnf_b);

    zero_acc_kernel<<<BATCH*DM/256, 256>>>();
    head_tc<<<dim3(DM/64, 28), 256>>>(hw);
    head_fin_kernel<<<BATCH*DM/256, 256>>>(hb, out);
}

// round 10
// speedup vs baseline: 4.1331x; 2.5500x over previous
// Resubmit of Round-9 fp16-WMMA kernel (bench infra failed twice with no
// diagnostics — same flake signature as R0/R2/R5; source re-audited:
// cp.async alignment, smem limits, group pairing all OK).
#include <cuda_runtime.h>
#include <cuda_fp16.h>
#include <mma.h>
#include <math.h>
#include <stdint.h>

using namespace nvcuda;

#define BATCH 256
#define SEQ   49
#define NTOK  (BATCH*SEQ)      // 12544
#define DM    1024
#define HDIM  512
#define NHEAD 2
#define KTOT  (SEQ*DM)         // 50176
#define EPS   1e-5f

// Scratch (static device globals; allocation APIs are forbidden)
__device__ float  g_h  [NTOK*DM];      // fp32 residual stream
__device__ float  g_hn [NTOK*DM];      // fp32 final-LN out (head input)
__device__ float  g_q  [NTOK*DM];
__device__ float  g_k  [NTOK*DM];
__device__ float  g_v  [NTOK*DM];
__device__ float  g_acc[BATCH*DM];
__device__ __half g_hnh[NTOK*DM];      // fp16 LN out (layer GEMM A)
__device__ __half g_ctxh[NTOK*DM];     // fp16 attention context
__device__ __half g_th [NTOK*DM];      // fp16 FFN mid
__device__ __half g_wh [12*DM*DM];     // fp16 layer weights [K,N], no transpose

__device__ __forceinline__ float to_tf32(float x) {
    uint32_t r;
    asm("cvt.rna.tf32.f32 %0, %1;" : "=r"(r) : "f"(x));
    return __uint_as_float(r);
}

// ---------------- cp.async helpers ----------------
__device__ __forceinline__ void cp16(void* s, const void* g) {
    uint32_t sa = (uint32_t)__cvta_generic_to_shared(s);
    asm volatile("cp.async.cg.shared.global [%0], [%1], 16;" :: "r"(sa), "l"(g));
}
__device__ __forceinline__ void cp_commit() {
    asm volatile("cp.async.commit_group;");
}
__device__ __forceinline__ void cp_wait1() {
    asm volatile("cp.async.wait_group 1;");
}
__device__ __forceinline__ void cp_wait0() {
    asm volatile("cp.async.wait_group 0;");
}

// ---------------------------------------------------------------------------
// Embed: h[b,s,d] = x[b,d,s] + pos[s,d]
// ---------------------------------------------------------------------------
__global__ void embed_kernel(const float* __restrict__ x,
                             const float* __restrict__ pos) {
    __shared__ float tile[32][33];
    int b  = blockIdx.z;
    int s0 = blockIdx.y * 32;
    int d0 = blockIdx.x * 32;
    int tx = threadIdx.x, ty = threadIdx.y;

    if (s0 + tx < SEQ)
        tile[ty][tx] = x[(size_t)b*DM*SEQ + (size_t)(d0+ty)*SEQ + (s0+tx)];
    __syncthreads();
    int ss = s0 + ty, dd = d0 + tx;
    if (ss < SEQ)
        g_h[((size_t)b*SEQ + ss)*DM + dd] = tile[tx][ty] + pos[(size_t)ss*DM + dd];
}

// ---------------------------------------------------------------------------
// Weight -> fp16 conversion (rne), layout preserved [K,N].
// z = layer*6 + {0:q,1:k,2:v,3:o,4:w1,5:w2}
// ---------------------------------------------------------------------------
__global__ void convert_wh(const float* __restrict__ wq, const float* __restrict__ wk,
                           const float* __restrict__ wv, const float* __restrict__ wo,
                           const float* __restrict__ w1, const float* __restrict__ w2) {
    int z = blockIdx.y, layer = z / 6, m = z % 6;
    const float* src;
    switch (m) {
        case 0: src = wq; break;  case 1: src = wk; break;
        case 2: src = wv; break;  case 3: src = wo; break;
        case 4: src = w1; break;  default: src = w2; break;
    }
    src += (size_t)layer * DM * DM;
    __half* dst = g_wh + (size_t)z * DM * DM;
    int idx = (blockIdx.x * 256 + threadIdx.x) * 4;
    float4 v = *reinterpret_cast<const float4*>(&src[idx]);
    __half2 lo = __floats2half2_rn(v.x, v.y);
    __half2 hi = __floats2half2_rn(v.z, v.w);
    *reinterpret_cast<__half2*>(&dst[idx])     = lo;
    *reinterpret_cast<__half2*>(&dst[idx + 2]) = hi;
}

// ---------------------------------------------------------------------------
// LayerNorm per row of 1024: fp16 output (feeds layer GEMMs as A)
// ---------------------------------------------------------------------------
__global__ void ln16_kernel(const float* __restrict__ in, __half* __restrict__ out,
                            const float* __restrict__ sc, const float* __restrict__ bi) {
    int r = blockIdx.x;
    const float* row = in + (size_t)r*DM;
    float v[4];
    float s = 0.f, sq = 0.f;
#pragma unroll
    for (int i = 0; i < 4; i++) {
        v[i] = row[threadIdx.x + i*256];
        s += v[i]; sq += v[i]*v[i];
    }
#pragma unroll
    for (int o = 16; o > 0; o >>= 1) {
        s  += __shfl_xor_sync(0xffffffffu, s,  o);
        sq += __shfl_xor_sync(0xffffffffu, sq, o);
    }
    __shared__ float sh[2][8];
    int w = threadIdx.x >> 5, l = threadIdx.x & 31;
    if (l == 0) { sh[0][w] = s; sh[1][w] = sq; }
    __syncthreads();
    s = 0.f; sq = 0.f;
#pragma unroll
    for (int i = 0; i < 8; i++) { s += sh[0][i]; sq += sh[1][i]; }
    float mean = s * (1.f/1024.f);
    float var  = sq * (1.f/1024.f) - mean*mean;
    float rstd = rsqrtf(var + EPS);
#pragma unroll
    for (int i = 0; i < 4; i++) {
        int d = threadIdx.x + i*256;
        out[(size_t)r*DM + d] = __float2half_rn((v[i] - mean) * rstd * sc[d] + bi[d]);
    }
}

// fp32(tf32-rounded) output variant — final LN only (feeds head)
__global__ void ln_kernel(const float* __restrict__ in, float* __restrict__ out,
                          const float* __restrict__ sc, const float* __restrict__ bi) {
    int r = blockIdx.x;
    const float* row = in + (size_t)r*DM;
    float v[4];
    float s = 0.f, sq = 0.f;
#pragma unroll
    for (int i = 0; i < 4; i++) {
        v[i] = row[threadIdx.x + i*256];
        s += v[i]; sq += v[i]*v[i];
    }
#pragma unroll
    for (int o = 16; o > 0; o >>= 1) {
        s  += __shfl_xor_sync(0xffffffffu, s,  o);
        sq += __shfl_xor_sync(0xffffffffu, sq, o);
    }
    __shared__ float sh[2][8];
    int w = threadIdx.x >> 5, l = threadIdx.x & 31;
    if (l == 0) { sh[0][w] = s; sh[1][w] = sq; }
    __syncthreads();
    s = 0.f; sq = 0.f;
#pragma unroll
    for (int i = 0; i < 8; i++) { s += sh[0][i]; sq += sh[1][i]; }
    float mean = s * (1.f/1024.f);
    float var  = sq * (1.f/1024.f) - mean*mean;
    float rstd = rsqrtf(var + EPS);
#pragma unroll
    for (int i = 0; i < 4; i++) {
        int d = threadIdx.x + i*256;
        out[(size_t)r*DM + d] = to_tf32((v[i] - mean) * rstd * sc[d] + bi[d]);
    }
}

__device__ __forceinline__ float gelu_tanh(float x) {
    float x3 = x*x*x;
    return 0.5f * x * (1.f + tanhf(0.7978845608028654f * (x + 0.044715f*x3)));
}

// ---------------------------------------------------------------------------
// fp16 WMMA GEMM: C = epi(A[M,K]h @ B[K,N]h), fp32 accumulate.
// BM=128, BN=64, BK=32.  256 threads = 8 warps 4x2; warp tile 32x32
// = 2x2 wmma(16x16x16).  3-stage cp.async.  LDSM fragment loads.
// ---------------------------------------------------------------------------
#define FALD 40                 // A pitch in halves (80B rows)
#define FBLD 72                 // B pitch in halves (144B rows)
#define FASZ (128*FALD)         // 5120 halves
#define FBSZ (32*FBLD)          // 2304 halves
#define FSTG (FASZ+FBSZ)        // 7424 halves = 14848 B
#define FSM  (3*FSTG)           // 22272 halves = 44544 B
#define FELD 36                 // fp32 epilogue scratch pitch

template<bool RES, bool BIAS, bool GELU, bool OUTH>
__device__ __forceinline__ void gemmh_core(
        const __half* __restrict__ A, const __half* __restrict__ Bw,
        const float* __restrict__ Rs, const float* __restrict__ bias,
        void* __restrict__ Cv, int N, int K, int bm, int bn, __half* sm) {
    int tid = threadIdx.x;
    int warp = tid >> 5, lane = tid & 31;
    int wm = warp & 3;    // rows wm*32
    int wn = warp >> 2;   // cols wn*32

    wmma::fragment<wmma::accumulator,16,16,16,float> acc[2][2];
#pragma unroll
    for (int i = 0; i < 2; i++)
#pragma unroll
        for (int j = 0; j < 2; j++) wmma::fill_fragment(acc[i][j], 0.f);

    auto stage = [&](int buf, int k0) {
        __half* As = sm + buf*FSTG;
        __half* Bs = As + FASZ;
#pragma unroll
        for (int i = 0; i < 2; i++) {          // A: 512 cp16 (8 halves each)
            int e = tid + i*256;
            int r = e >> 2, c8 = (e & 3) * 8;
            cp16(&As[r*FALD + c8], A + (size_t)(bm + r)*K + k0 + c8);
        }
        {                                       // B: 256 cp16
            int r = tid >> 3, c8 = (tid & 7) * 8;
            cp16(&Bs[r*FBLD + c8], Bw + (size_t)(k0 + r)*N + bn + c8);
        }
    };

    const int T = K >> 5;   // 32
    stage(0, 0);  cp_commit();
    stage(1, 32); cp_commit();

#pragma unroll 1
    for (int t = 0; t < T; t++) {
        cp_wait1();
        __syncthreads();
        if (t + 2 < T) { stage((t+2)%3, (t+2) << 5); cp_commit(); }
        __half* As = sm + (t%3)*FSTG;
        __half* Bs = As + FASZ;
#pragma unroll
        for (int ks = 0; ks < 2; ks++) {
            wmma::fragment<wmma::matrix_a,16,16,16,__half,wmma::row_major> fa[2];
            wmma::fragment<wmma::matrix_b,16,16,16,__half,wmma::row_major> fb[2];
#pragma unroll
            for (int i = 0; i < 2; i++)
                wmma::load_matrix_sync(fa[i], &As[(wm*32 + i*16)*FALD + ks*16], FALD);
#pragma unroll
            for (int j = 0; j < 2; j++)
                wmma::load_matrix_sync(fb[j], &Bs[(ks*16)*FBLD + wn*32 + j*16], FBLD);
#pragma unroll
            for (int i = 0; i < 2; i++)
#pragma unroll
                for (int j = 0; j < 2; j++)
                    wmma::mma_sync(acc[i][j], fa[i], fb[j], acc[i][j]);
        }
        __syncthreads();   // done reading buffer t%3 before it is re-staged
    }

    // epilogue via fp32 smem scratch
    float* scf = reinterpret_cast<float*>(sm) + warp * (16*FELD);  // 8*576 fp32
#pragma unroll 1
    for (int i = 0; i < 2; i++) {
#pragma unroll
        for (int j = 0; j < 2; j++)
            wmma::store_matrix_sync(scf + j*16, acc[i][j], FELD, wmma::mem_row_major);
        __syncwarp();
        int row0 = bm + wm*32 + i*16;
        int col0 = bn + wn*32;
#pragma unroll
        for (int e = lane; e < 128; e += 32) {   // 16 rows x 8 quads
            int r = e >> 3, c4 = (e & 7) * 4;
            float o[4];
#pragma unroll
            for (int j = 0; j < 4; j++) o[j] = scf[r*FELD + c4 + j];
            if (BIAS) {
                float4 bb = *reinterpret_cast<const float4*>(&bias[col0 + c4]);
                o[0] += bb.x; o[1] += bb.y; o[2] += bb.z; o[3] += bb.w;
            }
            if (GELU) {
#pragma unroll
                for (int j = 0; j < 4; j++) o[j] = gelu_tanh(o[j]);
            }
            size_t off = (size_t)(row0 + r)*N + col0 + c4;
            if (RES) {
                float4 r4 = *reinterpret_cast<const float4*>(&Rs[off]);
                o[0] += r4.x; o[1] += r4.y; o[2] += r4.z; o[3] += r4.w;
            }
            if (OUTH) {
                __half* Ch = reinterpret_cast<__half*>(Cv);
                *reinterpret_cast<__half2*>(&Ch[off])     = __floats2half2_rn(o[0], o[1]);
                *reinterpret_cast<__half2*>(&Ch[off + 2]) = __floats2half2_rn(o[2], o[3]);
            } else {
                float* Cf = reinterpret_cast<float*>(Cv);
                *reinterpret_cast<float4*>(&Cf[off]) = make_float4(o[0], o[1], o[2], o[3]);
            }
        }
        __syncwarp();
    }
}

template<bool RES, bool BIAS, bool GELU, bool OUTH>
__global__ void __launch_bounds__(256) gemm_h(
        const __half* __restrict__ A, const __half* __restrict__ Bw,
        const float* __restrict__ Rs, const float* __restrict__ bias,
        void* __restrict__ C) {
    __shared__ __align__(16) __half sm[FSM];
    gemmh_core<RES,BIAS,GELU,OUTH>(A, Bw, Rs, bias, C, DM, DM,
                                   blockIdx.y*128, blockIdx.x*64, sm);
}

// Fused QKV: blockIdx.x in [0,48): sel = x>>4 picks weight/output, (x&15)->bn.
__global__ void __launch_bounds__(256) gemm_h_qkv(
        const __half* __restrict__ A, const __half* __restrict__ BtBase,
        float* __restrict__ C0, float* __restrict__ C1, float* __restrict__ C2) {
    __shared__ __align__(16) __half sm[FSM];
    int sel = blockIdx.x >> 4;
    const __half* Bw = BtBase + (size_t)sel * DM * DM;
    float* C = (sel == 0) ? C0 : (sel == 1) ? C1 : C2;
    gemmh_core<false,false,false,false>(A, Bw, nullptr, nullptr, C, DM, DM,
                                        blockIdx.y*128, (blockIdx.x & 15)*64, sm);
}

// ---------------------------------------------------------------------------
// Fused attention per (b, head).  512 threads.  ctx written as fp16.
// ---------------------------------------------------------------------------
__global__ void attn_kernel() {
    int bh = blockIdx.x;
    int b = bh >> 1, h = bh & 1;
    __shared__ float sc[SEQ*SEQ];
    __shared__ float qs[SEQ][65];
    __shared__ float ks[SEQ][65];
    int tid = threadIdx.x;

    const float* qbase = g_q + ((size_t)b*SEQ)*DM + h*HDIM;
    const float* kbase = g_k + ((size_t)b*SEQ)*DM + h*HDIM;
    const float* vbase = g_v + ((size_t)b*SEQ)*DM + h*HDIM;

    int q  = tid / 10;
    int k0 = (tid % 10) * 5;
    bool act = (q < SEQ);
    int qc = act ? q : SEQ-1;
    float acc5[5] = {0.f,0.f,0.f,0.f,0.f};
    for (int c0 = 0; c0 < HDIM; c0 += 64) {
        for (int e = tid; e < SEQ*64; e += 512) {
            int r = e >> 6, c = e & 63;
            qs[r][c] = qbase[(size_t)r*DM + c0 + c];
            ks[r][c] = kbase[(size_t)r*DM + c0 + c];
        }
        __syncthreads();
#pragma unroll 4
        for (int c = 0; c < 64; c++) {
            float qv = qs[qc][c];
#pragma unroll
            for (int j = 0; j < 5; j++) {
                int kk = k0 + j; if (kk > SEQ-1) kk = SEQ-1;
                acc5[j] += qv * ks[kk][c];
            }
        }
        __syncthreads();
    }
    const float scale = 0.044194173824159216f;
    if (act) {
#pragma unroll
        for (int j = 0; j < 5; j++) {
            int kk = k0 + j;
            if (kk < SEQ) sc[q*SEQ + kk] = acc5[j] * scale;
        }
    }
    __syncthreads();

    {
        int warp = tid >> 5, lane = tid & 31;
        for (int row = warp; row < SEQ; row += 16) {
            float v0 = (lane      < SEQ) ? sc[row*SEQ + lane]      : -1e30f;
            float v1 = (lane + 32 < SEQ) ? sc[row*SEQ + lane + 32] : -1e30f;
            float m = fmaxf(v0, v1);
#pragma unroll
            for (int o = 16; o > 0; o >>= 1)
                m = fmaxf(m, __shfl_xor_sync(0xffffffffu, m, o));
            float e0 = (lane      < SEQ) ? expf(v0 - m) : 0.f;
            float e1 = (lane + 32 < SEQ) ? expf(v1 - m) : 0.f;
            float s = e0 + e1;
#pragma unroll
            for (int o = 16; o > 0; o >>= 1)
                s += __shfl_xor_sync(0xffffffffu, s, o);
            float inv = 1.f / s;
            if (lane      < SEQ) sc[row*SEQ + lane]      = e0 * inv;
            if (lane + 32 < SEQ) sc[row*SEQ + lane + 32] = e1 * inv;
        }
    }
    __syncthreads();

    {
        float a[SEQ];
#pragma unroll
        for (int qq = 0; qq < SEQ; qq++) a[qq] = 0.f;
        for (int k = 0; k < SEQ; k++) {
            float vv = vbase[(size_t)k*DM + tid];
#pragma unroll
            for (int qq = 0; qq < SEQ; qq++)
                a[qq] += sc[qq*SEQ + k] * vv;
        }
        __half* cb = g_ctxh + ((size_t)b*SEQ)*DM + h*HDIM + tid;
#pragma unroll
        for (int qq = 0; qq < SEQ; qq++)
            cb[(size_t)qq*DM] = __float2half_rn(a[qq]);
    }
}

// ---------------------------------------------------------------------------
// Head GEMM (TF32 WMMA, DRAM-bound): unchanged.  Reads fp32 g_hn.
// ---------------------------------------------------------------------------
#define HALD 16
#define HBLD 68
#define HASZ (256*HALD)
#define HBSZ (16*HBLD)
#define HELD 36
#define HSM  (2*HASZ + 2*HBSZ)

__global__ void __launch_bounds__(256) head_tc(const float* __restrict__ W) {
    __shared__ __align__(16) float hsm[HSM];
    float* AsBase = hsm;
    float* BsBase = hsm + 2*HASZ;

    int bn = blockIdx.x * 64;
    int kbase = blockIdx.y * 1792;
    int tid = threadIdx.x;
    int warp = tid >> 5, lane = tid & 31;
    int wm = warp & 3;
    int wn = warp >> 2;

    wmma::fragment<wmma::accumulator,16,16,8,float> acc[4][2];
#pragma unroll
    for (int i = 0; i < 4; i++)
#pragma unroll
        for (int j = 0; j < 2; j++) wmma::fill_fragment(acc[i][j], 0.f);

    auto stage = [&](int buf, int k0) {
        float* As = AsBase + buf*HASZ;
        float* Bs = BsBase + buf*HBSZ;
#pragma unroll
        for (int i = 0; i < 4; i++) {
            int e = tid + i*256;
            int r = e >> 2, c4 = (e & 3) * 4;
            cp16(&As[r*HALD + c4], &g_hn[(size_t)r*KTOT + k0 + c4]);
        }
        {
            int r = tid >> 4, c4 = (tid & 15) * 4;
            cp16(&Bs[r*HBLD + c4], &W[(size_t)(k0 + r)*DM + bn + c4]);
        }
    };

    stage(0, kbase);
    cp_commit();

    int buf = 0;
#pragma unroll 1
    for (int t = 0; t < 112; t++) {
        cp_wait0();
        __syncthreads();
        if (t < 111) { stage(buf ^ 1, kbase + (t+1)*16); cp_commit(); }
        float* As = AsBase + buf*HASZ;
        float* Bs = BsBase + buf*HBSZ;
#pragma unroll
        for (int ks = 0; ks < 2; ks++) {
            wmma::fragment<wmma::matrix_a,16,16,8,wmma::precision::tf32,wmma::row_major> fa[4];
            wmma::fragment<wmma::matrix_b,16,16,8,wmma::precision::tf32,wmma::row_major> fb[2];
#pragma unroll
            for (int i = 0; i < 4; i++)
                wmma::load_matrix_sync(fa[i], &As[(wm*64 + i*16)*HALD + ks*8], HALD);
#pragma unroll
            for (int j = 0; j < 2; j++) {
                wmma::load_matrix_sync(fb[j], &Bs[(ks*8)*HBLD + wn*32 + j*16], HBLD);
#pragma unroll
                for (int e = 0; e < fb[j].num_elements; e++)
                    fb[j].x[e] = to_tf32(fb[j].x[e]);
            }
#pragma unroll
            for (int i = 0; i < 4; i++)
#pragma unroll
                for (int j = 0; j < 2; j++)
                    wmma::mma_sync(acc[i][j], fa[i], fb[j], acc[i][j]);
        }
        buf ^= 1;
    }
    __syncthreads();

    float* sc = hsm + warp * (16*HELD);
#pragma unroll 1
    for (int i = 0; i < 4; i++) {
#pragma unroll
        for (int j = 0; j < 2; j++)
            wmma::store_matrix_sync(sc + j*16, acc[i][j], HELD, wmma::mem_row_major);
        __syncwarp();
        int row0 = wm*64 + i*16;
        int col0 = bn + wn*32;
#pragma unroll
        for (int e = lane; e < 512; e += 32) {
            int r = e >> 5, c = e & 31;
            atomicAdd(&g_acc[(size_t)(row0 + r)*DM + col0 + c], sc[r*HELD + c]);
        }
        __syncwarp();
    }
}

__global__ void zero_acc_kernel() {
    g_acc[blockIdx.x*256 + threadIdx.x] = 0.f;
}

__global__ void head_fin_kernel(const float* __restrict__ hb, float* __restrict__ out) {
    int i = blockIdx.x*256 + threadIdx.x;
    float v = g_acc[i] + hb[i & (DM-1)];
    out[i] = v > 0.f ? v : 0.f;
}

// ---------------------------------------------------------------------------
// Launch
// ---------------------------------------------------------------------------
extern "C" void kernel_launch(void* const* d_in, const int* in_sizes, int n_in,
                              void* d_out, int out_size) {
    const float* x     = (const float*)d_in[0];
    const float* pos   = (const float*)d_in[1];
    const float* ln1_s = (const float*)d_in[2];
    const float* ln1_b = (const float*)d_in[3];
    const float* wq    = (const float*)d_in[4];
    const float* wk    = (const float*)d_in[5];
    const float* wv    = (const float*)d_in[6];
    const float* wo    = (const float*)d_in[7];
    const float* ln2_s = (const float*)d_in[8];
    const float* ln2_b = (const float*)d_in[9];
    const float* w1    = (const float*)d_in[10];
    const float* b1    = (const float*)d_in[11];
    const float* w2    = (const float*)d_in[12];
    const float* b2    = (const float*)d_in[13];
    const float* lnf_s = (const float*)d_in[14];
    const float* lnf_b = (const float*)d_in[15];
    const float* hw    = (const float*)d_in[16];
    const float* hb    = (const float*)d_in[17];
    float* out = (float*)d_out;

    float *h, *hn, *q, *k, *v;
    __half *hnh, *ctxh, *th, *wh;
    cudaGetSymbolAddress((void**)&h,    g_h);
    cudaGetSymbolAddress((void**)&hn,   g_hn);
    cudaGetSymbolAddress((void**)&q,    g_q);
    cudaGetSymbolAddress((void**)&k,    g_k);
    cudaGetSymbolAddress((void**)&v,    g_v);
    cudaGetSymbolAddress((void**)&hnh,  g_hnh);
    cudaGetSymbolAddress((void**)&ctxh, g_ctxh);
    cudaGetSymbolAddress((void**)&th,   g_th);
    cudaGetSymbolAddress((void**)&wh,   g_wh);

    embed_kernel<<<dim3(32, 2, BATCH), dim3(32, 32)>>>(x, pos);
    convert_wh<<<dim3(1024, 12), 256>>>(wq, wk, wv, wo, w1, w2);

    dim3 gg(DM/64, NTOK/128);     // (16, 98)
    dim3 gq(3*DM/64, NTOK/128);   // (48, 98)
    for (int i = 0; i < 2; i++) {
        const __half* whL = wh + (size_t)i*6*DM*DM;
        ln16_kernel<<<NTOK, 256>>>(h, hnh, ln1_s + i*DM, ln1_b + i*DM);
        gemm_h_qkv<<<gq, 256>>>(hnh, whL, q, k, v);
        attn_kernel<<<BATCH*NHEAD, 512>>>();
        gemm_h<true,false,false,false><<<gg, 256>>>(ctxh, whL + 3*(size_t)DM*DM, h, nullptr, h);
        ln16_kernel<<<NTOK, 256>>>(h, hnh, ln2_s + i*DM, ln2_b + i*DM);
        gemm_h<false,true,true,true><<<gg, 256>>>(hnh, whL + 4*(size_t)DM*DM, nullptr, b1 + i*DM, th);
        gemm_h<true,true,false,false><<<gg, 256>>>(th, whL + 5*(size_t)DM*DM, h, b2 + i*DM, h);
    }
    ln_kernel<<<NTOK, 256>>>(h, hn, lnf_s, lnf_b);

    zero_acc_kernel<<<BATCH*DM/256, 256>>>();
    head_tc<<<dim3(DM/64, 28), 256>>>(hw);
    head_fin_kernel<<<BATCH*DM/256, 256>>>(hb, out);
}

// round 12
// speedup vs baseline: 4.4170x; 1.0687x over previous
// Resubmit of Round-11 kernel (bench infra "failed twice" with no diagnostics
// — same flake signature as R0/R2/R5/R9, each of which passed on resubmit).
// Source re-audited: cp.async alignment (272B B-pitch), smem 37.9KB static,
// occupancy request 2x75.8KB < 228KB, group pairing balanced.
#include <cuda_runtime.h>
#include <cuda_fp16.h>
#include <mma.h>
#include <math.h>
#include <stdint.h>

using namespace nvcuda;

#define BATCH 256
#define SEQ   49
#define NTOK  (BATCH*SEQ)      // 12544
#define DM    1024
#define HDIM  512
#define NHEAD 2
#define KTOT  (SEQ*DM)         // 50176
#define EPS   1e-5f

// Scratch (static device globals; allocation APIs are forbidden)
__device__ float  g_h  [NTOK*DM];      // fp32 residual stream
__device__ float  g_hn [NTOK*DM];      // fp32 final-LN out (head input)
__device__ float  g_acc[BATCH*DM];
__device__ __half g_qh [NTOK*DM];      // fp16 q/k/v
__device__ __half g_kh [NTOK*DM];
__device__ __half g_vh [NTOK*DM];
__device__ __half g_hnh[NTOK*DM];      // fp16 LN out (layer GEMM A)
__device__ __half g_ctxh[NTOK*DM];     // fp16 attention context
__device__ __half g_th [NTOK*DM];      // fp16 FFN mid
__device__ __half g_wh [12*DM*DM];     // fp16 layer weights [K,N]

__device__ __forceinline__ float to_tf32(float x) {
    uint32_t r;
    asm("cvt.rna.tf32.f32 %0, %1;" : "=r"(r) : "f"(x));
    return __uint_as_float(r);
}

// ---------------- cp.async helpers ----------------
__device__ __forceinline__ void cp16(void* s, const void* g) {
    uint32_t sa = (uint32_t)__cvta_generic_to_shared(s);
    asm volatile("cp.async.cg.shared.global [%0], [%1], 16;" :: "r"(sa), "l"(g));
}
__device__ __forceinline__ void cp_commit() {
    asm volatile("cp.async.commit_group;");
}
__device__ __forceinline__ void cp_wait0() {
    asm volatile("cp.async.wait_group 0;");
}

// ---------------------------------------------------------------------------
// Embed: h[b,s,d] = x[b,d,s] + pos[s,d]
// ---------------------------------------------------------------------------
__global__ void embed_kernel(const float* __restrict__ x,
                             const float* __restrict__ pos) {
    __shared__ float tile[32][33];
    int b  = blockIdx.z;
    int s0 = blockIdx.y * 32;
    int d0 = blockIdx.x * 32;
    int tx = threadIdx.x, ty = threadIdx.y;

    if (s0 + tx < SEQ)
        tile[ty][tx] = x[(size_t)b*DM*SEQ + (size_t)(d0+ty)*SEQ + (s0+tx)];
    __syncthreads();
    int ss = s0 + ty, dd = d0 + tx;
    if (ss < SEQ)
        g_h[((size_t)b*SEQ + ss)*DM + dd] = tile[tx][ty] + pos[(size_t)ss*DM + dd];
}

// ---------------------------------------------------------------------------
// Weight -> fp16 conversion (rne), layout preserved [K,N].
// ---------------------------------------------------------------------------
__global__ void convert_wh(const float* __restrict__ wq, const float* __restrict__ wk,
                           const float* __restrict__ wv, const float* __restrict__ wo,
                           const float* __restrict__ w1, const float* __restrict__ w2) {
    int z = blockIdx.y, layer = z / 6, m = z % 6;
    const float* src;
    switch (m) {
        case 0: src = wq; break;  case 1: src = wk; break;
        case 2: src = wv; break;  case 3: src = wo; break;
        case 4: src = w1; break;  default: src = w2; break;
    }
    src += (size_t)layer * DM * DM;
    __half* dst = g_wh + (size_t)z * DM * DM;
    int idx = (blockIdx.x * 256 + threadIdx.x) * 4;
    float4 v = *reinterpret_cast<const float4*>(&src[idx]);
    *reinterpret_cast<__half2*>(&dst[idx])     = __floats2half2_rn(v.x, v.y);
    *reinterpret_cast<__half2*>(&dst[idx + 2]) = __floats2half2_rn(v.z, v.w);
}

// ---------------------------------------------------------------------------
// LayerNorm (fp16 out) — feeds layer GEMMs
// ---------------------------------------------------------------------------
__global__ void ln16_kernel(const float* __restrict__ in, __half* __restrict__ out,
                            const float* __restrict__ sc, const float* __restrict__ bi) {
    int r = blockIdx.x;
    const float* row = in + (size_t)r*DM;
    float v[4];
    float s = 0.f, sq = 0.f;
#pragma unroll
    for (int i = 0; i < 4; i++) {
        v[i] = row[threadIdx.x + i*256];
        s += v[i]; sq += v[i]*v[i];
    }
#pragma unroll
    for (int o = 16; o > 0; o >>= 1) {
        s  += __shfl_xor_sync(0xffffffffu, s,  o);
        sq += __shfl_xor_sync(0xffffffffu, sq, o);
    }
    __shared__ float sh[2][8];
    int w = threadIdx.x >> 5, l = threadIdx.x & 31;
    if (l == 0) { sh[0][w] = s; sh[1][w] = sq; }
    __syncthreads();
    s = 0.f; sq = 0.f;
#pragma unroll
    for (int i = 0; i < 8; i++) { s += sh[0][i]; sq += sh[1][i]; }
    float mean = s * (1.f/1024.f);
    float var  = sq * (1.f/1024.f) - mean*mean;
    float rstd = rsqrtf(var + EPS);
#pragma unroll
    for (int i = 0; i < 4; i++) {
        int d = threadIdx.x + i*256;
        out[(size_t)r*DM + d] = __float2half_rn((v[i] - mean) * rstd * sc[d] + bi[d]);
    }
}

// fp32(tf32-rounded) variant — final LN only (feeds head)
__global__ void ln_kernel(const float* __restrict__ in, float* __restrict__ out,
                          const float* __restrict__ sc, const float* __restrict__ bi) {
    int r = blockIdx.x;
    const float* row = in + (size_t)r*DM;
    float v[4];
    float s = 0.f, sq = 0.f;
#pragma unroll
    for (int i = 0; i < 4; i++) {
        v[i] = row[threadIdx.x + i*256];
        s += v[i]; sq += v[i]*v[i];
    }
#pragma unroll
    for (int o = 16; o > 0; o >>= 1) {
        s  += __shfl_xor_sync(0xffffffffu, s,  o);
        sq += __shfl_xor_sync(0xffffffffu, sq, o);
    }
    __shared__ float sh[2][8];
    int w = threadIdx.x >> 5, l = threadIdx.x & 31;
    if (l == 0) { sh[0][w] = s; sh[1][w] = sq; }
    __syncthreads();
    s = 0.f; sq = 0.f;
#pragma unroll
    for (int i = 0; i < 8; i++) { s += sh[0][i]; sq += sh[1][i]; }
    float mean = s * (1.f/1024.f);
    float var  = sq * (1.f/1024.f) - mean*mean;
    float rstd = rsqrtf(var + EPS);
#pragma unroll
    for (int i = 0; i < 4; i++) {
        int d = threadIdx.x + i*256;
        out[(size_t)r*DM + d] = to_tf32((v[i] - mean) * rstd * sc[d] + bi[d]);
    }
}

__device__ __forceinline__ float gelu_tanh(float x) {
    float x3 = x*x*x;
    return 0.5f * x * (1.f + tanhf(0.7978845608028654f * (x + 0.044715f*x3)));
}

// ---------------------------------------------------------------------------
// fp16 WMMA GEMM: C = epi(A[M,K]h @ B[K,N]h), fp32 accumulate.
// BM=128, BN=128, BK=32.  256 threads = 8 warps in 2x4; warp tile 64x32
// = 4x2 wmma(16x16x16).  2-stage cp.async, ONE __syncthreads per K-tile.
// ---------------------------------------------------------------------------
#define FALD 40                 // A pitch in halves (80B rows)
#define FBLD 136                // B pitch in halves (272B rows)
#define FASZ (128*FALD)         // 5120 halves
#define FBSZ (32*FBLD)          // 4352 halves
#define FSTG (FASZ+FBSZ)        // 9472 halves = 18944 B
#define FSM  (2*FSTG)           // 18944 halves = 37888 B
#define FELD 36                 // fp32 epilogue scratch pitch

template<bool RES, bool BIAS, bool GELU, bool OUTH>
__device__ __forceinline__ void gemmh_core(
        const __half* __restrict__ A, const __half* __restrict__ Bw,
        const float* __restrict__ Rs, const float* __restrict__ bias,
        void* __restrict__ Cv, int N, int K, int bm, int bn, __half* sm) {
    int tid = threadIdx.x;
    int warp = tid >> 5, lane = tid & 31;
    int wm = warp >> 2;   // 0..1 -> rows wm*64
    int wn = warp & 3;    // 0..3 -> cols wn*32

    wmma::fragment<wmma::accumulator,16,16,16,float> acc[4][2];
#pragma unroll
    for (int i = 0; i < 4; i++)
#pragma unroll
        for (int j = 0; j < 2; j++) wmma::fill_fragment(acc[i][j], 0.f);

    auto stage = [&](int buf, int k0) {
        __half* As = sm + buf*FSTG;
        __half* Bs = As + FASZ;
#pragma unroll
        for (int i = 0; i < 2; i++) {          // A: 128x32 halves = 512 cp16
            int e = tid + i*256;
            int r = e >> 2, c8 = (e & 3) * 8;
            cp16(&As[r*FALD + c8], A + (size_t)(bm + r)*K + k0 + c8);
        }
#pragma unroll
        for (int i = 0; i < 2; i++) {          // B: 32x128 halves = 512 cp16
            int e = tid + i*256;
            int r = e >> 4, c8 = (e & 15) * 8;
            cp16(&Bs[r*FBLD + c8], Bw + (size_t)(k0 + r)*N + bn + c8);
        }
    };

    const int T = K >> 5;   // 32
    stage(0, 0);  cp_commit();

#pragma unroll 1
    for (int t = 0; t < T; t++) {
        cp_wait0();
        __syncthreads();    // also orders last iter's compute before restage
        if (t + 1 < T) { stage((t+1) & 1, (t+1) << 5); cp_commit(); }
        __half* As = sm + (t & 1)*FSTG;
        __half* Bs = As + FASZ;
#pragma unroll
        for (int ks = 0; ks < 2; ks++) {
            wmma::fragment<wmma::matrix_a,16,16,16,__half,wmma::row_major> fa[4];
            wmma::fragment<wmma::matrix_b,16,16,16,__half,wmma::row_major> fb[2];
#pragma unroll
            for (int i = 0; i < 4; i++)
                wmma::load_matrix_sync(fa[i], &As[(wm*64 + i*16)*FALD + ks*16], FALD);
#pragma unroll
            for (int j = 0; j < 2; j++)
                wmma::load_matrix_sync(fb[j], &Bs[(ks*16)*FBLD + wn*32 + j*16], FBLD);
#pragma unroll
            for (int i = 0; i < 4; i++)
#pragma unroll
                for (int j = 0; j < 2; j++)
                    wmma::mma_sync(acc[i][j], fa[i], fb[j], acc[i][j]);
        }
    }
    __syncthreads();        // all compute done before smem reuse as scratch

    // epilogue via fp32 smem scratch
    float* scf = reinterpret_cast<float*>(sm) + warp * (16*FELD);  // 8*576 fp32
#pragma unroll 1
    for (int i = 0; i < 4; i++) {
#pragma unroll
        for (int j = 0; j < 2; j++)
            wmma::store_matrix_sync(scf + j*16, acc[i][j], FELD, wmma::mem_row_major);
        __syncwarp();
        int row0 = bm + wm*64 + i*16;
        int col0 = bn + wn*32;
#pragma unroll
        for (int e = lane; e < 128; e += 32) {   // 16 rows x 8 quads
            int r = e >> 3, c4 = (e & 7) * 4;
            float o[4];
#pragma unroll
            for (int j = 0; j < 4; j++) o[j] = scf[r*FELD + c4 + j];
            if (BIAS) {
                float4 bb = *reinterpret_cast<const float4*>(&bias[col0 + c4]);
                o[0] += bb.x; o[1] += bb.y; o[2] += bb.z; o[3] += bb.w;
            }
            if (GELU) {
#pragma unroll
                for (int j = 0; j < 4; j++) o[j] = gelu_tanh(o[j]);
            }
            size_t off = (size_t)(row0 + r)*N + col0 + c4;
            if (RES) {
                float4 r4 = *reinterpret_cast<const float4*>(&Rs[off]);
                o[0] += r4.x; o[1] += r4.y; o[2] += r4.z; o[3] += r4.w;
            }
            if (OUTH) {
                __half* Ch = reinterpret_cast<__half*>(Cv);
                *reinterpret_cast<__half2*>(&Ch[off])     = __floats2half2_rn(o[0], o[1]);
                *reinterpret_cast<__half2*>(&Ch[off + 2]) = __floats2half2_rn(o[2], o[3]);
            } else {
                float* Cf = reinterpret_cast<float*>(Cv);
                *reinterpret_cast<float4*>(&Cf[off]) = make_float4(o[0], o[1], o[2], o[3]);
            }
        }
        __syncwarp();
    }
}

template<bool RES, bool BIAS, bool GELU, bool OUTH>
__global__ void __launch_bounds__(256, 2) gemm_h(
        const __half* __restrict__ A, const __half* __restrict__ Bw,
        const float* __restrict__ Rs, const float* __restrict__ bias,
        void* __restrict__ C) {
    __shared__ __align__(16) __half sm[FSM];
    gemmh_core<RES,BIAS,GELU,OUTH>(A, Bw, Rs, bias, C, DM, DM,
                                   blockIdx.y*128, blockIdx.x*128, sm);
}

// Fused QKV (fp16 outputs): blockIdx.x in [0,24): sel=x>>3, (x&7)->bn.
__global__ void __launch_bounds__(256, 2) gemm_h_qkv(
        const __half* __restrict__ A, const __half* __restrict__ BtBase,
        __half* __restrict__ C0, __half* __restrict__ C1, __half* __restrict__ C2) {
    __shared__ __align__(16) __half sm[FSM];
    int sel = blockIdx.x >> 3;
    const __half* Bw = BtBase + (size_t)sel * DM * DM;
    __half* C = (sel == 0) ? C0 : (sel == 1) ? C1 : C2;
    gemmh_core<false,false,false,true>(A, Bw, nullptr, nullptr, C, DM, DM,
                                       blockIdx.y*128, (blockIdx.x & 7)*128, sm);
}

// ---------------------------------------------------------------------------
// Fused attention per (b, head).  512 threads.  fp16 q/k/v in, fp16 ctx out.
// ---------------------------------------------------------------------------
__global__ void attn_kernel() {
    int bh = blockIdx.x;
    int b = bh >> 1, h = bh & 1;
    __shared__ float sc[SEQ*SEQ];
    __shared__ float qs[SEQ][65];
    __shared__ float ks[SEQ][65];
    int tid = threadIdx.x;

    const __half* qbase = g_qh + ((size_t)b*SEQ)*DM + h*HDIM;
    const __half* kbase = g_kh + ((size_t)b*SEQ)*DM + h*HDIM;
    const __half* vbase = g_vh + ((size_t)b*SEQ)*DM + h*HDIM;

    int q  = tid / 10;
    int k0 = (tid % 10) * 5;
    bool act = (q < SEQ);
    int qc = act ? q : SEQ-1;
    float acc5[5] = {0.f,0.f,0.f,0.f,0.f};
    for (int c0 = 0; c0 < HDIM; c0 += 64) {
        for (int e = tid; e < SEQ*32; e += 512) {
            int r = e / 32, c2 = (e % 32) * 2;
            __half2 qv = *reinterpret_cast<const __half2*>(&qbase[(size_t)r*DM + c0 + c2]);
            __half2 kv = *reinterpret_cast<const __half2*>(&kbase[(size_t)r*DM + c0 + c2]);
            float2 qf = __half22float2(qv);
            float2 kf = __half22float2(kv);
            qs[r][c2] = qf.x; qs[r][c2+1] = qf.y;
            ks[r][c2] = kf.x; ks[r][c2+1] = kf.y;
        }
        __syncthreads();
#pragma unroll 4
        for (int c = 0; c < 64; c++) {
            float qv = qs[qc][c];
#pragma unroll
            for (int j = 0; j < 5; j++) {
                int kk = k0 + j; if (kk > SEQ-1) kk = SEQ-1;
                acc5[j] += qv * ks[kk][c];
            }
        }
        __syncthreads();
    }
    const float scale = 0.044194173824159216f;
    if (act) {
#pragma unroll
        for (int j = 0; j < 5; j++) {
            int kk = k0 + j;
            if (kk < SEQ) sc[q*SEQ + kk] = acc5[j] * scale;
        }
    }
    __syncthreads();

    {
        int warp = tid >> 5, lane = tid & 31;
        for (int row = warp; row < SEQ; row += 16) {
            float v0 = (lane      < SEQ) ? sc[row*SEQ + lane]      : -1e30f;
            float v1 = (lane + 32 < SEQ) ? sc[row*SEQ + lane + 32] : -1e30f;
            float m = fmaxf(v0, v1);
#pragma unroll
            for (int o = 16; o > 0; o >>= 1)
                m = fmaxf(m, __shfl_xor_sync(0xffffffffu, m, o));
            float e0 = (lane      < SEQ) ? expf(v0 - m) : 0.f;
            float e1 = (lane + 32 < SEQ) ? expf(v1 - m) : 0.f;
            float s = e0 + e1;
#pragma unroll
            for (int o = 16; o > 0; o >>= 1)
                s += __shfl_xor_sync(0xffffffffu, s, o);
            float inv = 1.f / s;
            if (lane      < SEQ) sc[row*SEQ + lane]      = e0 * inv;
            if (lane + 32 < SEQ) sc[row*SEQ + lane + 32] = e1 * inv;
        }
    }
    __syncthreads();

    {
        float a[SEQ];
#pragma unroll
        for (int qq = 0; qq < SEQ; qq++) a[qq] = 0.f;
        for (int k = 0; k < SEQ; k++) {
            float vv = __half2float(vbase[(size_t)k*DM + tid]);
#pragma unroll
            for (int qq = 0; qq < SEQ; qq++)
                a[qq] += sc[qq*SEQ + k] * vv;
        }
        __half* cb = g_ctxh + ((size_t)b*SEQ)*DM + h*HDIM + tid;
#pragma unroll
        for (int qq = 0; qq < SEQ; qq++)
            cb[(size_t)qq*DM] = __float2half_rn(a[qq]);
    }
}

// ---------------------------------------------------------------------------
// Head GEMM (TF32 WMMA, DRAM-bound): unchanged.  Reads fp32 g_hn.
// ---------------------------------------------------------------------------
#define HALD 16
#define HBLD 68
#define HASZ (256*HALD)
#define HBSZ (16*HBLD)
#define HELD 36
#define HSM  (2*HASZ + 2*HBSZ)

__global__ void __launch_bounds__(256) head_tc(const float* __restrict__ W) {
    __shared__ __align__(16) float hsm[HSM];
    float* AsBase = hsm;
    float* BsBase = hsm + 2*HASZ;

    int bn = blockIdx.x * 64;
    int kbase = blockIdx.y * 1792;
    int tid = threadIdx.x;
    int warp = tid >> 5, lane = tid & 31;
    int wm = warp & 3;
    int wn = warp >> 2;

    wmma::fragment<wmma::accumulator,16,16,8,float> acc[4][2];
#pragma unroll
    for (int i = 0; i < 4; i++)
#pragma unroll
        for (int j = 0; j < 2; j++) wmma::fill_fragment(acc[i][j], 0.f);

    auto stage = [&](int buf, int k0) {
        float* As = AsBase + buf*HASZ;
        float* Bs = BsBase + buf*HBSZ;
#pragma unroll
        for (int i = 0; i < 4; i++) {
            int e = tid + i*256;
            int r = e >> 2, c4 = (e & 3) * 4;
            cp16(&As[r*HALD + c4], &g_hn[(size_t)r*KTOT + k0 + c4]);
        }
        {
            int r = tid >> 4, c4 = (tid & 15) * 4;
            cp16(&Bs[r*HBLD + c4], &W[(size_t)(k0 + r)*DM + bn + c4]);
        }
    };

    stage(0, kbase);
    cp_commit();

    int buf = 0;
#pragma unroll 1
    for (int t = 0; t < 112; t++) {
        cp_wait0();
        __syncthreads();
        if (t < 111) { stage(buf ^ 1, kbase + (t+1)*16); cp_commit(); }
        float* As = AsBase + buf*HASZ;
        float* Bs = BsBase + buf*HBSZ;
#pragma unroll
        for (int ks = 0; ks < 2; ks++) {
            wmma::fragment<wmma::matrix_a,16,16,8,wmma::precision::tf32,wmma::row_major> fa[4];
            wmma::fragment<wmma::matrix_b,16,16,8,wmma::precision::tf32,wmma::row_major> fb[2];
#pragma unroll
            for (int i = 0; i < 4; i++)
                wmma::load_matrix_sync(fa[i], &As[(wm*64 + i*16)*HALD + ks*8], HALD);
#pragma unroll
            for (int j = 0; j < 2; j++) {
                wmma::load_matrix_sync(fb[j], &Bs[(ks*8)*HBLD + wn*32 + j*16], HBLD);
#pragma unroll
                for (int e = 0; e < fb[j].num_elements; e++)
                    fb[j].x[e] = to_tf32(fb[j].x[e]);
            }
#pragma unroll
            for (int i = 0; i < 4; i++)
#pragma unroll
                for (int j = 0; j < 2; j++)
                    wmma::mma_sync(acc[i][j], fa[i], fb[j], acc[i][j]);
        }
        buf ^= 1;
    }
    __syncthreads();

    float* sc = hsm + warp * (16*HELD);
#pragma unroll 1
    for (int i = 0; i < 4; i++) {
#pragma unroll
        for (int j = 0; j < 2; j++)
            wmma::store_matrix_sync(sc + j*16, acc[i][j], HELD, wmma::mem_row_major);
        __syncwarp();
        int row0 = wm*64 + i*16;
        int col0 = bn + wn*32;
#pragma unroll
        for (int e = lane; e < 512; e += 32) {
            int r = e >> 5, c = e & 31;
            atomicAdd(&g_acc[(size_t)(row0 + r)*DM + col0 + c], sc[r*HELD + c]);
        }
        __syncwarp();
    }
}

__global__ void zero_acc_kernel() {
    g_acc[blockIdx.x*256 + threadIdx.x] = 0.f;
}

__global__ void head_fin_kernel(const float* __restrict__ hb, float* __restrict__ out) {
    int i = blockIdx.x*256 + threadIdx.x;
    float v = g_acc[i] + hb[i & (DM-1)];
    out[i] = v > 0.f ? v : 0.f;
}

// ---------------------------------------------------------------------------
// Launch
// ---------------------------------------------------------------------------
extern "C" void kernel_launch(void* const* d_in, const int* in_sizes, int n_in,
                              void* d_out, int out_size) {
    const float* x     = (const float*)d_in[0];
    const float* pos   = (const float*)d_in[1];
    const float* ln1_s = (const float*)d_in[2];
    const float* ln1_b = (const float*)d_in[3];
    const float* wq    = (const float*)d_in[4];
    const float* wk    = (const float*)d_in[5];
    const float* wv    = (const float*)d_in[6];
    const float* wo    = (const float*)d_in[7];
    const float* ln2_s = (const float*)d_in[8];
    const float* ln2_b = (const float*)d_in[9];
    const float* w1    = (const float*)d_in[10];
    const float* b1    = (const float*)d_in[11];
    const float* w2    = (const float*)d_in[12];
    const float* b2    = (const float*)d_in[13];
    const float* lnf_s = (const float*)d_in[14];
    const float* lnf_b = (const float*)d_in[15];
    const float* hw    = (const float*)d_in[16];
    const float* hb    = (const float*)d_in[17];
    float* out = (float*)d_out;

    float *h, *hn;
    __half *qh, *kh, *vh, *hnh, *ctxh, *th, *wh;
    cudaGetSymbolAddress((void**)&h,    g_h);
    cudaGetSymbolAddress((void**)&hn,   g_hn);
    cudaGetSymbolAddress((void**)&qh,   g_qh);
    cudaGetSymbolAddress((void**)&kh,   g_kh);
    cudaGetSymbolAddress((void**)&vh,   g_vh);
    cudaGetSymbolAddress((void**)&hnh,  g_hnh);
    cudaGetSymbolAddress((void**)&ctxh, g_ctxh);
    cudaGetSymbolAddress((void**)&th,   g_th);
    cudaGetSymbolAddress((void**)&wh,   g_wh);

    embed_kernel<<<dim3(32, 2, BATCH), dim3(32, 32)>>>(x, pos);
    convert_wh<<<dim3(1024, 12), 256>>>(wq, wk, wv, wo, w1, w2);

    dim3 gg(DM/128, NTOK/128);     // (8, 98)
    dim3 gq(3*DM/128, NTOK/128);   // (24, 98)
    for (int i = 0; i < 2; i++) {
        const __half* whL = wh + (size_t)i*6*DM*DM;
        ln16_kernel<<<NTOK, 256>>>(h, hnh, ln1_s + i*DM, ln1_b + i*DM);
        gemm_h_qkv<<<gq, 256>>>(hnh, whL, qh, kh, vh);
        attn_kernel<<<BATCH*NHEAD, 512>>>();
        gemm_h<true,false,false,false><<<gg, 256>>>(ctxh, whL + 3*(size_t)DM*DM, h, nullptr, h);
        ln16_kernel<<<NTOK, 256>>>(h, hnh, ln2_s + i*DM, ln2_b + i*DM);
        gemm_h<false,true,true,true><<<gg, 256>>>(hnh, whL + 4*(size_t)DM*DM, nullptr, b1 + i*DM, th);
        gemm_h<true,true,false,false><<<gg, 256>>>(th, whL + 5*(size_t)DM*DM, h, b2 + i*DM, h);
    }
    ln_kernel<<<NTOK, 256>>>(h, hn, lnf_s, lnf_b);

    zero_acc_kernel<<<BATCH*DM/256, 256>>>();
    head_tc<<<dim3(DM/64, 28), 256>>>(hw);
    head_fin_kernel<<<BATCH*DM/256, 256>>>(hb, out);
}